// round 12
// baseline (speedup 1.0000x reference)
#include <cuda_runtime.h>
#include <cuda_fp16.h>
#include <cstdint>

#define L_DIM 2048
#define N_DIM 4
#define E_DIM 1024
#define H_DIM 8
#define M1    (L_DIM * N_DIM)   // 8192
#define F3    (3 * E_DIM)       // 3072

// ------------------------------------------------------------------
// Scratch (__device__ globals; allocation-free)
// ------------------------------------------------------------------
__device__ __half g_xh  [(long long)M1 * E_DIM];
__device__ __half g_wqkv[(long long)H_DIM * F3 * E_DIM];
__device__ __half g_wo  [(long long)H_DIM * E_DIM * E_DIM];
__device__ __half g_qkv [(long long)H_DIM * M1 * F3];
__device__ float  g_scores[(long long)H_DIM * N_DIM * L_DIM * L_DIM];
__device__ __half g_attn[(long long)H_DIM * N_DIM * L_DIM * L_DIM];
__device__ __half g_ctx [(long long)H_DIM * M1 * E_DIM];

// ------------------------------------------------------------------
// Tile config: block 128x128, BK=64, 3-stage cp.async,
// 4 warps (128 thr), warp tile 64x64.
// ------------------------------------------------------------------
#define BM 128
#define BN 128
#define BK 64
#define NSTAGE 3
#define NTHR 128

#define A_SLOT_B 16384
#define B_SLOT_B 16384
#define STAGE_B  (A_SLOT_B + B_SLOT_B)
#define SMEM_DYN (NSTAGE * STAGE_B)   // 98304 B

// ------------------------------------------------------------------
// PTX helpers
// ------------------------------------------------------------------
__device__ __forceinline__ uint32_t smem_u32(const void* p) {
    uint32_t a;
    asm("{ .reg .u64 t; cvta.to.shared.u64 t, %1; cvt.u32.u64 %0, t; }" : "=r"(a) : "l"(p));
    return a;
}
__device__ __forceinline__ void cp_async16(uint32_t dst, const void* src) {
    asm volatile("cp.async.cg.shared.global [%0], [%1], 16;" :: "r"(dst), "l"(src));
}
__device__ __forceinline__ void ldsm_x4(uint32_t& r0, uint32_t& r1, uint32_t& r2, uint32_t& r3,
                                        uint32_t addr) {
    asm volatile("ldmatrix.sync.aligned.m8n8.x4.shared.b16 {%0,%1,%2,%3}, [%4];"
                 : "=r"(r0), "=r"(r1), "=r"(r2), "=r"(r3) : "r"(addr));
}
__device__ __forceinline__ void ldsm_x4_t(uint32_t& r0, uint32_t& r1, uint32_t& r2, uint32_t& r3,
                                          uint32_t addr) {
    asm volatile("ldmatrix.sync.aligned.m8n8.x4.trans.shared.b16 {%0,%1,%2,%3}, [%4];"
                 : "=r"(r0), "=r"(r1), "=r"(r2), "=r"(r3) : "r"(addr));
}
__device__ __forceinline__ void mma_f16(float c[4], const uint32_t a[4], const uint32_t b[2]) {
    asm volatile(
        "mma.sync.aligned.m16n8k16.row.col.f32.f16.f16.f32 "
        "{%0,%1,%2,%3}, {%4,%5,%6,%7}, {%8,%9}, {%0,%1,%2,%3};"
        : "+f"(c[0]), "+f"(c[1]), "+f"(c[2]), "+f"(c[3])
        : "r"(a[0]), "r"(a[1]), "r"(a[2]), "r"(a[3]), "r"(b[0]), "r"(b[1]));
}

// Swizzled byte offsets (rows of 128B: 8 x 16B chunks, chunk ^= row&7)
__device__ __forceinline__ uint32_t sw_ab(int row, int kc) {
    return (uint32_t)(row * 128 + ((((kc >> 3) & 7) ^ (row & 7)) << 4));
}
// kn layout: 64 rows x 256B
__device__ __forceinline__ uint32_t sw_kn(int krow, int nc) {
    return (uint32_t)(krow * 256 + ((nc >> 6) << 7) + ((((nc >> 3) & 7) ^ (krow & 7)) << 4));
}

// ------------------------------------------------------------------
// Templated GEMM. STAGE:
//  1: qkv(h) = x @ Wqkv^T + bqkv       A[m][k] B[n][k]  -> C fp16
//  2: scores = scale * q @ k^T         strided fp16     -> C fp32
//  3: ctx(h) = attn @ V                B is [k][n]      -> C fp16
//  4: out = sum_h ctx[h]@Wo[h]^T + b   K loop over h    -> C fp32
// ------------------------------------------------------------------
template <int STAGE>
__global__ void __launch_bounds__(NTHR, 2) gemm_mma(
    const __half* __restrict__ Ain, const __half* __restrict__ Bin,
    const float* __restrict__ bias, void* __restrict__ Cout)
{
    constexpr bool BKN = (STAGE == 3);
    constexpr bool CH  = (STAGE == 1 || STAGE == 3);
    constexpr int  NKT = (STAGE == 3) ? (L_DIM / BK)
                        : (STAGE == 4 ? H_DIM * (E_DIM / BK) : (E_DIM / BK));
    constexpr float alpha = (STAGE == 2) ? 0.03125f : 1.0f;

    extern __shared__ __align__(1024) char smem[];
    __shared__ float s_bias[BN];

    const int tid  = threadIdx.x;
    const int warp = tid >> 5;
    const int lane = tid & 31;
    const int wm   = warp >> 1;
    const int wn   = warp & 1;
    const int n0   = blockIdx.x * BN;
    const int m0   = blockIdx.y * BM;
    const int bz   = blockIdx.z;
    const int h    = bz >> 2;
    const int nn   = bz & 3;

    const uint32_t s_base = smem_u32(smem);

    for (int i = tid; i < BN; i += NTHR) {
        if (STAGE == 1) {
            s_bias[i] = bias[(long long)bz * F3 + n0 + i];
        } else if (STAGE == 4) {
            float s = 0.f;
            #pragma unroll
            for (int hh = 0; hh < H_DIM; hh++) s += bias[(long long)hh * E_DIM + n0 + i];
            s_bias[i] = s;
        } else {
            s_bias[i] = 0.f;
        }
    }

    const __half* Ab;
    const __half* Bb;
    long long ldA, ldB;
    if (STAGE == 1) {
        Ab = Ain;                                ldA = E_DIM;
        Bb = Bin + (long long)bz * F3 * E_DIM;   ldB = E_DIM;
    } else if (STAGE == 2) {
        const __half* q = Ain + (long long)h * M1 * F3 + (long long)nn * F3;
        Ab = q;          ldA = (long long)N_DIM * F3;
        Bb = q + E_DIM;  ldB = (long long)N_DIM * F3;
    } else if (STAGE == 3) {
        Ab = Ain + (long long)bz * L_DIM * L_DIM;                           ldA = L_DIM;
        Bb = Bin + (long long)h * M1 * F3 + (long long)nn * F3 + 2 * E_DIM; ldB = (long long)N_DIM * F3;
    } else {
        Ab = Ain; ldA = E_DIM;
        Bb = Bin; ldB = E_DIM;
    }

    auto load_tile = [&](int kt, int slot) {
        const __half* Abase = Ab;
        const __half* Bbase = Bb;
        int kk;
        if (STAGE == 4) {
            const int hh = kt >> 4;
            kk = (kt & 15) * BK;
            Abase = Ab + (long long)hh * M1 * E_DIM;
            Bbase = Bb + (long long)hh * E_DIM * E_DIM;
        } else {
            kk = kt * BK;
        }
        const uint32_t a_sl = s_base + slot * STAGE_B;
        const uint32_t b_sl = a_sl + A_SLOT_B;
        #pragma unroll
        for (int i = 0; i < 8; i++) {
            const int c = tid + i * NTHR;
            const int row = c >> 3;
            const int kc = (c & 7) << 3;
            const __half* src = Abase + (long long)(m0 + row) * ldA + kk + kc;
            cp_async16(a_sl + sw_ab(row, kc), src);
        }
        if (!BKN) {
            #pragma unroll
            for (int i = 0; i < 8; i++) {
                const int c = tid + i * NTHR;
                const int row = c >> 3;
                const int kc = (c & 7) << 3;
                const __half* src = Bbase + (long long)(n0 + row) * ldB + kk + kc;
                cp_async16(b_sl + sw_ab(row, kc), src);
            }
        } else {
            #pragma unroll
            for (int i = 0; i < 8; i++) {
                const int c = tid + i * NTHR;
                const int krow = c >> 4;
                const int nc = (c & 15) << 3;
                const __half* src = Bbase + (long long)(kk + krow) * ldB + n0 + nc;
                cp_async16(b_sl + sw_kn(krow, nc), src);
            }
        }
        asm volatile("cp.async.commit_group;" ::: "memory");
    };

    float acc[4][8][4] = {};

    load_tile(0, 0);
    load_tile(1, 1);
    asm volatile("cp.async.wait_group 1;" ::: "memory");
    __syncthreads();

    const int grp = lane >> 3;
    const int lr  = lane & 7;
    const int arow = lane & 15;
    const int asel = lane >> 4;

    // Ping-pong fragment buffers
    uint32_t afb[2][4][4];
    uint32_t bfb[2][8][2];

    auto load_frags = [&](uint32_t As, uint32_t Bs, int ks, int buf) {
        #pragma unroll
        for (int mi = 0; mi < 4; mi++) {
            const int row = wm * 64 + mi * 16 + arow;
            const int kc = ks * 16 + asel * 8;
            ldsm_x4(afb[buf][mi][0], afb[buf][mi][1], afb[buf][mi][2], afb[buf][mi][3],
                    As + sw_ab(row, kc));
        }
        #pragma unroll
        for (int pair = 0; pair < 4; pair++) {
            uint32_t r0, r1, r2, r3;
            if (!BKN) {
                const int nrow = wn * 64 + pair * 16 + ((grp >> 1) << 3) + lr;
                const int kc = ks * 16 + ((grp & 1) << 3);
                ldsm_x4(r0, r1, r2, r3, Bs + sw_ab(nrow, kc));
            } else {
                const int krow = ks * 16 + ((grp & 1) << 3) + lr;
                const int ncol = wn * 64 + pair * 16 + ((grp >> 1) << 3);
                ldsm_x4_t(r0, r1, r2, r3, Bs + sw_kn(krow, ncol));
            }
            bfb[buf][pair * 2][0]     = r0;
            bfb[buf][pair * 2][1]     = r1;
            bfb[buf][pair * 2 + 1][0] = r2;
            bfb[buf][pair * 2 + 1][1] = r3;
        }
    };

    // Half-burst: 16 MMAs covering mi = {2*half, 2*half+1}, all ni.
    auto mma_half = [&](int buf, int half) {
        #pragma unroll
        for (int mi = 2 * half; mi < 2 * half + 2; mi++)
            #pragma unroll
            for (int ni = 0; ni < 8; ni++)
                mma_f16(acc[mi][ni], afb[buf][mi], bfb[buf][ni]);
    };

    // Prologue: ks0 fragments of kt=0 pre-loaded into buffer 0.
    {
        const uint32_t As0 = s_base;
        load_frags(As0, As0 + A_SLOT_B, 0, 0);
    }

    for (int kt = 0; kt < NKT; kt++) {
        const int slot = kt % NSTAGE;
        const uint32_t As = s_base + slot * STAGE_B;
        const uint32_t Bs = As + A_SLOT_B;

        // Entry invariant: buf0 holds this kt's ks0 fragments.
        // Interleaved schedule: every LDSM batch is sandwiched between
        // 16-MMA half-bursts already occupying the tensor pipe.
        mma_half(0, 0);                          // ks0 first half
        load_frags(As, Bs, 1, 1);                // ks1 -> b1
        mma_half(0, 1);                          // ks0 second half

        if (kt + 2 < NKT) load_tile(kt + 2, (kt + 2) % NSTAGE);

        load_frags(As, Bs, 2, 0);                // ks2 -> b0 (ks0 fully issued)
        mma_half(1, 0);                          // ks1 first half
        mma_half(1, 1);                          // ks1 second half
        load_frags(As, Bs, 3, 1);                // ks3 -> b1 (ks1 fully issued)
        mma_half(0, 0);                          // ks2 first half

        // Hoisted pipeline sync: drains under the remaining bursts.
        if (kt + 2 < NKT) {
            asm volatile("cp.async.wait_group 1;" ::: "memory");
        } else {
            asm volatile("cp.async.wait_group 0;" ::: "memory");
        }
        __syncthreads();

        mma_half(0, 1);                          // ks2 second half

        // Cross-kt prefetch (slot kt+1 complete, barrier passed).
        // Final iteration reads a stale-but-valid slot; never consumed.
        {
            const uint32_t nAs = s_base + ((kt + 1) % NSTAGE) * STAGE_B;
            load_frags(nAs, nAs + A_SLOT_B, 0, 0);
        }

        mma_half(1, 0);                          // ks3 first half
        mma_half(1, 1);                          // ks3 second half
    }

    // ---------------- epilogue ----------------
    const int r  = lane >> 2;
    const int cl = lane & 3;

    long long ldc, coff;
    if (STAGE == 1) {
        ldc = F3;    coff = ((long long)bz * M1 + m0) * F3 + n0;
    } else if (STAGE == 2) {
        ldc = L_DIM; coff = ((long long)bz * L_DIM + m0) * L_DIM + n0;
    } else if (STAGE == 3) {
        ldc = (long long)N_DIM * E_DIM;
        coff = (long long)h * M1 * E_DIM + ((long long)m0 * N_DIM + nn) * E_DIM + n0;
    } else {
        ldc = E_DIM; coff = (long long)m0 * E_DIM + n0;
    }

    #pragma unroll
    for (int mi = 0; mi < 4; mi++) {
        #pragma unroll
        for (int ni = 0; ni < 8; ni++) {
            const int row = wm * 64 + mi * 16 + r;
            const int col = wn * 64 + ni * 8 + cl * 2;
            const float v00 = acc[mi][ni][0] * alpha + s_bias[col];
            const float v01 = acc[mi][ni][1] * alpha + s_bias[col + 1];
            const float v10 = acc[mi][ni][2] * alpha + s_bias[col];
            const float v11 = acc[mi][ni][3] * alpha + s_bias[col + 1];
            if (CH) {
                __half* C = (__half*)Cout + coff;
                *reinterpret_cast<__half2*>(&C[(long long)row * ldc + col]) =
                    __floats2half2_rn(v00, v01);
                *reinterpret_cast<__half2*>(&C[(long long)(row + 8) * ldc + col]) =
                    __floats2half2_rn(v10, v11);
            } else {
                float* C = (float*)Cout + coff;
                *reinterpret_cast<float2*>(&C[(long long)row * ldc + col])       = make_float2(v00, v01);
                *reinterpret_cast<float2*>(&C[(long long)(row + 8) * ldc + col]) = make_float2(v10, v11);
            }
        }
    }
}

// ------------------------------------------------------------------
// fp32 -> fp16 convert
// ------------------------------------------------------------------
__global__ void __launch_bounds__(256) k_f2h(const float4* __restrict__ in,
                                             __half2* __restrict__ out, long long n4) {
    const long long i = (long long)blockIdx.x * blockDim.x + threadIdx.x;
    if (i < n4) {
        float4 v = in[i];
        out[2 * i]     = __floats2half2_rn(v.x, v.y);
        out[2 * i + 1] = __floats2half2_rn(v.z, v.w);
    }
}

// ------------------------------------------------------------------
// Softmax: fp32 scores -> fp16 probs
// ------------------------------------------------------------------
__global__ void __launch_bounds__(256) k_softmax(const float* __restrict__ S,
                                                 __half* __restrict__ P) {
    __shared__ float red_max[8];
    __shared__ float red_sum[8];
    const long long row = blockIdx.x;
    const float4* p = reinterpret_cast<const float4*>(S + row * (long long)L_DIM);
    const int t = threadIdx.x;
    float4 a = p[t];
    float4 b = p[t + 256];

    float m = fmaxf(fmaxf(fmaxf(a.x, a.y), fmaxf(a.z, a.w)),
                    fmaxf(fmaxf(b.x, b.y), fmaxf(b.z, b.w)));
    #pragma unroll
    for (int o = 16; o; o >>= 1) m = fmaxf(m, __shfl_xor_sync(0xFFFFFFFFu, m, o));
    if ((t & 31) == 0) red_max[t >> 5] = m;
    __syncthreads();
    float mall = red_max[0];
    #pragma unroll
    for (int i = 1; i < 8; i++) mall = fmaxf(mall, red_max[i]);

    a.x = __expf(a.x - mall); a.y = __expf(a.y - mall);
    a.z = __expf(a.z - mall); a.w = __expf(a.w - mall);
    b.x = __expf(b.x - mall); b.y = __expf(b.y - mall);
    b.z = __expf(b.z - mall); b.w = __expf(b.w - mall);

    float sum = a.x + a.y + a.z + a.w + b.x + b.y + b.z + b.w;
    #pragma unroll
    for (int o = 16; o; o >>= 1) sum += __shfl_xor_sync(0xFFFFFFFFu, sum, o);
    if ((t & 31) == 0) red_sum[t >> 5] = sum;
    __syncthreads();
    float stot = 0.f;
    #pragma unroll
    for (int i = 0; i < 8; i++) stot += red_sum[i];
    const float inv = 1.0f / stot;

    __half2* q = reinterpret_cast<__half2*>(P + row * (long long)L_DIM);
    q[2 * t]           = __floats2half2_rn(a.x * inv, a.y * inv);
    q[2 * t + 1]       = __floats2half2_rn(a.z * inv, a.w * inv);
    q[512 + 2 * t]     = __floats2half2_rn(b.x * inv, b.y * inv);
    q[512 + 2 * t + 1] = __floats2half2_rn(b.z * inv, b.w * inv);
}

// ------------------------------------------------------------------
// Host
// ------------------------------------------------------------------
extern "C" void kernel_launch(void* const* d_in, const int* in_sizes, int n_in,
                              void* d_out, int out_size) {
    const float* x    = (const float*)d_in[0];
    const float* Wqkv = (const float*)d_in[1];
    const float* bqkv = (const float*)d_in[2];
    const float* Wo   = (const float*)d_in[3];
    const float* bo   = (const float*)d_in[4];
    float* out = (float*)d_out;

    __half *xh, *wqkvh, *woh, *qkv, *attn, *ctx;
    float* scores;
    cudaGetSymbolAddress((void**)&xh, g_xh);
    cudaGetSymbolAddress((void**)&wqkvh, g_wqkv);
    cudaGetSymbolAddress((void**)&woh, g_wo);
    cudaGetSymbolAddress((void**)&qkv, g_qkv);
    cudaGetSymbolAddress((void**)&scores, g_scores);
    cudaGetSymbolAddress((void**)&attn, g_attn);
    cudaGetSymbolAddress((void**)&ctx, g_ctx);

    static bool attr_done = false;
    if (!attr_done) {
        cudaFuncSetAttribute(gemm_mma<1>, cudaFuncAttributeMaxDynamicSharedMemorySize, SMEM_DYN);
        cudaFuncSetAttribute(gemm_mma<2>, cudaFuncAttributeMaxDynamicSharedMemorySize, SMEM_DYN);
        cudaFuncSetAttribute(gemm_mma<3>, cudaFuncAttributeMaxDynamicSharedMemorySize, SMEM_DYN);
        cudaFuncSetAttribute(gemm_mma<4>, cudaFuncAttributeMaxDynamicSharedMemorySize, SMEM_DYN);
        attr_done = true;
    }

    {
        const long long nx = (long long)M1 * E_DIM / 4;
        const long long nw = (long long)H_DIM * F3 * E_DIM / 4;
        const long long no = (long long)H_DIM * E_DIM * E_DIM / 4;
        k_f2h<<<(unsigned)((nx + 255) / 256), 256>>>((const float4*)x, (__half2*)xh, nx);
        k_f2h<<<(unsigned)((nw + 255) / 256), 256>>>((const float4*)Wqkv, (__half2*)wqkvh, nw);
        k_f2h<<<(unsigned)((no + 255) / 256), 256>>>((const float4*)Wo, (__half2*)woh, no);
    }

    gemm_mma<1><<<dim3(F3 / BN, M1 / BM, H_DIM), NTHR, SMEM_DYN>>>(xh, wqkvh, bqkv, qkv);
    gemm_mma<2><<<dim3(L_DIM / BN, L_DIM / BM, H_DIM * N_DIM), NTHR, SMEM_DYN>>>(qkv, qkv, nullptr, scores);
    k_softmax<<<H_DIM * N_DIM * L_DIM, 256>>>(scores, attn);
    gemm_mma<3><<<dim3(E_DIM / BN, L_DIM / BM, H_DIM * N_DIM), NTHR, SMEM_DYN>>>(attn, qkv, nullptr, ctx);
    gemm_mma<4><<<dim3(E_DIM / BN, M1 / BM, 1), NTHR, SMEM_DYN>>>(ctx, woh, bo, out);
}

// round 14
// speedup vs baseline: 1.0062x; 1.0062x over previous
#include <cuda_runtime.h>
#include <cuda_fp16.h>
#include <cstdint>

#define L_DIM 2048
#define N_DIM 4
#define E_DIM 1024
#define H_DIM 8
#define M1    (L_DIM * N_DIM)   // 8192
#define F3    (3 * E_DIM)       // 3072

// ------------------------------------------------------------------
// Scratch (__device__ globals; allocation-free)
// ------------------------------------------------------------------
__device__ __half g_xh  [(long long)M1 * E_DIM];
__device__ __half g_wqkv[(long long)H_DIM * F3 * E_DIM];
__device__ __half g_wo  [(long long)H_DIM * E_DIM * E_DIM];
__device__ __half g_qkv [(long long)H_DIM * M1 * F3];
__device__ __half g_scores[(long long)H_DIM * N_DIM * L_DIM * L_DIM];  // fp16 scores
__device__ __half g_attn[(long long)H_DIM * N_DIM * L_DIM * L_DIM];
__device__ __half g_ctx [(long long)H_DIM * M1 * E_DIM];

// ------------------------------------------------------------------
// Tile config: block 128x128, BK=64, 3-stage cp.async,
// 4 warps (128 thr), warp tile 64x64.
// ------------------------------------------------------------------
#define BM 128
#define BN 128
#define BK 64
#define NSTAGE 3
#define NTHR 128

#define A_SLOT_B 16384
#define B_SLOT_B 16384
#define STAGE_B  (A_SLOT_B + B_SLOT_B)
#define SMEM_DYN (NSTAGE * STAGE_B)   // 98304 B

// ------------------------------------------------------------------
// PTX helpers
// ------------------------------------------------------------------
__device__ __forceinline__ uint32_t smem_u32(const void* p) {
    uint32_t a;
    asm("{ .reg .u64 t; cvta.to.shared.u64 t, %1; cvt.u32.u64 %0, t; }" : "=r"(a) : "l"(p));
    return a;
}
__device__ __forceinline__ void cp_async16(uint32_t dst, const void* src) {
    asm volatile("cp.async.cg.shared.global [%0], [%1], 16;" :: "r"(dst), "l"(src));
}
__device__ __forceinline__ void ldsm_x4(uint32_t& r0, uint32_t& r1, uint32_t& r2, uint32_t& r3,
                                        uint32_t addr) {
    asm volatile("ldmatrix.sync.aligned.m8n8.x4.shared.b16 {%0,%1,%2,%3}, [%4];"
                 : "=r"(r0), "=r"(r1), "=r"(r2), "=r"(r3) : "r"(addr));
}
__device__ __forceinline__ void ldsm_x4_t(uint32_t& r0, uint32_t& r1, uint32_t& r2, uint32_t& r3,
                                          uint32_t addr) {
    asm volatile("ldmatrix.sync.aligned.m8n8.x4.trans.shared.b16 {%0,%1,%2,%3}, [%4];"
                 : "=r"(r0), "=r"(r1), "=r"(r2), "=r"(r3) : "r"(addr));
}
__device__ __forceinline__ void mma_f16(float c[4], const uint32_t a[4], const uint32_t b[2]) {
    asm volatile(
        "mma.sync.aligned.m16n8k16.row.col.f32.f16.f16.f32 "
        "{%0,%1,%2,%3}, {%4,%5,%6,%7}, {%8,%9}, {%0,%1,%2,%3};"
        : "+f"(c[0]), "+f"(c[1]), "+f"(c[2]), "+f"(c[3])
        : "r"(a[0]), "r"(a[1]), "r"(a[2]), "r"(a[3]), "r"(b[0]), "r"(b[1]));
}

// Swizzled byte offsets (rows of 128B: 8 x 16B chunks, chunk ^= row&7)
__device__ __forceinline__ uint32_t sw_ab(int row, int kc) {
    return (uint32_t)(row * 128 + ((((kc >> 3) & 7) ^ (row & 7)) << 4));
}
// kn layout: 64 rows x 256B
__device__ __forceinline__ uint32_t sw_kn(int krow, int nc) {
    return (uint32_t)(krow * 256 + ((nc >> 6) << 7) + ((((nc >> 3) & 7) ^ (krow & 7)) << 4));
}

// ------------------------------------------------------------------
// Templated GEMM. STAGE:
//  1: qkv(h) = x @ Wqkv^T + bqkv       A[m][k] B[n][k]  -> C fp16
//  2: scores = scale * q @ k^T         strided fp16     -> C fp16
//  3: ctx(h) = attn @ V                B is [k][n]      -> C fp16
//  4: out = sum_h ctx[h]@Wo[h]^T + b   K loop over h    -> C fp32
// ------------------------------------------------------------------
template <int STAGE>
__global__ void __launch_bounds__(NTHR, 2) gemm_mma(
    const __half* __restrict__ Ain, const __half* __restrict__ Bin,
    const float* __restrict__ bias, void* __restrict__ Cout)
{
    constexpr bool BKN = (STAGE == 3);
    constexpr bool CH  = (STAGE != 4);   // fp16 output for stages 1,2,3
    constexpr int  NKT = (STAGE == 3) ? (L_DIM / BK)
                        : (STAGE == 4 ? H_DIM * (E_DIM / BK) : (E_DIM / BK));
    constexpr float alpha = (STAGE == 2) ? 0.03125f : 1.0f;

    extern __shared__ __align__(1024) char smem[];
    __shared__ float s_bias[BN];

    const int tid  = threadIdx.x;
    const int warp = tid >> 5;
    const int lane = tid & 31;
    const int wm   = warp >> 1;
    const int wn   = warp & 1;
    const int n0   = blockIdx.x * BN;
    const int m0   = blockIdx.y * BM;
    const int bz   = blockIdx.z;
    const int h    = bz >> 2;
    const int nn   = bz & 3;

    const uint32_t s_base = smem_u32(smem);

    for (int i = tid; i < BN; i += NTHR) {
        if (STAGE == 1) {
            s_bias[i] = bias[(long long)bz * F3 + n0 + i];
        } else if (STAGE == 4) {
            float s = 0.f;
            #pragma unroll
            for (int hh = 0; hh < H_DIM; hh++) s += bias[(long long)hh * E_DIM + n0 + i];
            s_bias[i] = s;
        } else {
            s_bias[i] = 0.f;
        }
    }

    const __half* Ab;
    const __half* Bb;
    long long ldA, ldB;
    if (STAGE == 1) {
        Ab = Ain;                                ldA = E_DIM;
        Bb = Bin + (long long)bz * F3 * E_DIM;   ldB = E_DIM;
    } else if (STAGE == 2) {
        const __half* q = Ain + (long long)h * M1 * F3 + (long long)nn * F3;
        Ab = q;          ldA = (long long)N_DIM * F3;
        Bb = q + E_DIM;  ldB = (long long)N_DIM * F3;
    } else if (STAGE == 3) {
        Ab = Ain + (long long)bz * L_DIM * L_DIM;                           ldA = L_DIM;
        Bb = Bin + (long long)h * M1 * F3 + (long long)nn * F3 + 2 * E_DIM; ldB = (long long)N_DIM * F3;
    } else {
        Ab = Ain; ldA = E_DIM;
        Bb = Bin; ldB = E_DIM;
    }

    auto load_tile = [&](int kt, int slot) {
        const __half* Abase = Ab;
        const __half* Bbase = Bb;
        int kk;
        if (STAGE == 4) {
            const int hh = kt >> 4;
            kk = (kt & 15) * BK;
            Abase = Ab + (long long)hh * M1 * E_DIM;
            Bbase = Bb + (long long)hh * E_DIM * E_DIM;
        } else {
            kk = kt * BK;
        }
        const uint32_t a_sl = s_base + slot * STAGE_B;
        const uint32_t b_sl = a_sl + A_SLOT_B;
        #pragma unroll
        for (int i = 0; i < 8; i++) {
            const int c = tid + i * NTHR;
            const int row = c >> 3;
            const int kc = (c & 7) << 3;
            const __half* src = Abase + (long long)(m0 + row) * ldA + kk + kc;
            cp_async16(a_sl + sw_ab(row, kc), src);
        }
        if (!BKN) {
            #pragma unroll
            for (int i = 0; i < 8; i++) {
                const int c = tid + i * NTHR;
                const int row = c >> 3;
                const int kc = (c & 7) << 3;
                const __half* src = Bbase + (long long)(n0 + row) * ldB + kk + kc;
                cp_async16(b_sl + sw_ab(row, kc), src);
            }
        } else {
            #pragma unroll
            for (int i = 0; i < 8; i++) {
                const int c = tid + i * NTHR;
                const int krow = c >> 4;
                const int nc = (c & 15) << 3;
                const __half* src = Bbase + (long long)(kk + krow) * ldB + n0 + nc;
                cp_async16(b_sl + sw_kn(krow, nc), src);
            }
        }
        asm volatile("cp.async.commit_group;" ::: "memory");
    };

    float acc[4][8][4] = {};

    load_tile(0, 0);
    load_tile(1, 1);
    asm volatile("cp.async.wait_group 1;" ::: "memory");
    __syncthreads();

    const int grp = lane >> 3;
    const int lr  = lane & 7;
    const int arow = lane & 15;
    const int asel = lane >> 4;

    // Ping-pong fragment buffers
    uint32_t afb[2][4][4];
    uint32_t bfb[2][8][2];

    auto load_frags = [&](uint32_t As, uint32_t Bs, int ks, int buf) {
        #pragma unroll
        for (int mi = 0; mi < 4; mi++) {
            const int row = wm * 64 + mi * 16 + arow;
            const int kc = ks * 16 + asel * 8;
            ldsm_x4(afb[buf][mi][0], afb[buf][mi][1], afb[buf][mi][2], afb[buf][mi][3],
                    As + sw_ab(row, kc));
        }
        #pragma unroll
        for (int pair = 0; pair < 4; pair++) {
            uint32_t r0, r1, r2, r3;
            if (!BKN) {
                const int nrow = wn * 64 + pair * 16 + ((grp >> 1) << 3) + lr;
                const int kc = ks * 16 + ((grp & 1) << 3);
                ldsm_x4(r0, r1, r2, r3, Bs + sw_ab(nrow, kc));
            } else {
                const int krow = ks * 16 + ((grp & 1) << 3) + lr;
                const int ncol = wn * 64 + pair * 16 + ((grp >> 1) << 3);
                ldsm_x4_t(r0, r1, r2, r3, Bs + sw_kn(krow, ncol));
            }
            bfb[buf][pair * 2][0]     = r0;
            bfb[buf][pair * 2][1]     = r1;
            bfb[buf][pair * 2 + 1][0] = r2;
            bfb[buf][pair * 2 + 1][1] = r3;
        }
    };

    // Half-burst: 16 MMAs covering mi = {2*half, 2*half+1}, all ni.
    auto mma_half = [&](int buf, int half) {
        #pragma unroll
        for (int mi = 2 * half; mi < 2 * half + 2; mi++)
            #pragma unroll
            for (int ni = 0; ni < 8; ni++)
                mma_f16(acc[mi][ni], afb[buf][mi], bfb[buf][ni]);
    };

    // Prologue: ks0 fragments of kt=0 pre-loaded into buffer 0.
    {
        const uint32_t As0 = s_base;
        load_frags(As0, As0 + A_SLOT_B, 0, 0);
    }

    for (int kt = 0; kt < NKT; kt++) {
        const int slot = kt % NSTAGE;
        const uint32_t As = s_base + slot * STAGE_B;
        const uint32_t Bs = As + A_SLOT_B;

        mma_half(0, 0);                          // ks0 first half
        load_frags(As, Bs, 1, 1);                // ks1 -> b1
        mma_half(0, 1);                          // ks0 second half

        if (kt + 2 < NKT) load_tile(kt + 2, (kt + 2) % NSTAGE);

        load_frags(As, Bs, 2, 0);                // ks2 -> b0
        mma_half(1, 0);                          // ks1 first half
        mma_half(1, 1);                          // ks1 second half
        load_frags(As, Bs, 3, 1);                // ks3 -> b1
        mma_half(0, 0);                          // ks2 first half

        if (kt + 2 < NKT) {
            asm volatile("cp.async.wait_group 1;" ::: "memory");
        } else {
            asm volatile("cp.async.wait_group 0;" ::: "memory");
        }
        __syncthreads();

        mma_half(0, 1);                          // ks2 second half

        // Cross-kt prefetch (slot kt+1 complete, barrier passed).
        {
            const uint32_t nAs = s_base + ((kt + 1) % NSTAGE) * STAGE_B;
            load_frags(nAs, nAs + A_SLOT_B, 0, 0);
        }

        mma_half(1, 0);                          // ks3 first half
        mma_half(1, 1);                          // ks3 second half
    }

    // ---------------- epilogue ----------------
    const int r  = lane >> 2;
    const int cl = lane & 3;

    long long ldc, coff;
    if (STAGE == 1) {
        ldc = F3;    coff = ((long long)bz * M1 + m0) * F3 + n0;
    } else if (STAGE == 2) {
        ldc = L_DIM; coff = ((long long)bz * L_DIM + m0) * L_DIM + n0;
    } else if (STAGE == 3) {
        ldc = (long long)N_DIM * E_DIM;
        coff = (long long)h * M1 * E_DIM + ((long long)m0 * N_DIM + nn) * E_DIM + n0;
    } else {
        ldc = E_DIM; coff = (long long)m0 * E_DIM + n0;
    }

    #pragma unroll
    for (int mi = 0; mi < 4; mi++) {
        #pragma unroll
        for (int ni = 0; ni < 8; ni++) {
            const int row = wm * 64 + mi * 16 + r;
            const int col = wn * 64 + ni * 8 + cl * 2;
            const float v00 = acc[mi][ni][0] * alpha + s_bias[col];
            const float v01 = acc[mi][ni][1] * alpha + s_bias[col + 1];
            const float v10 = acc[mi][ni][2] * alpha + s_bias[col];
            const float v11 = acc[mi][ni][3] * alpha + s_bias[col + 1];
            if (CH) {
                __half* C = (__half*)Cout + coff;
                *reinterpret_cast<__half2*>(&C[(long long)row * ldc + col]) =
                    __floats2half2_rn(v00, v01);
                *reinterpret_cast<__half2*>(&C[(long long)(row + 8) * ldc + col]) =
                    __floats2half2_rn(v10, v11);
            } else {
                float* C = (float*)Cout + coff;
                *reinterpret_cast<float2*>(&C[(long long)row * ldc + col])       = make_float2(v00, v01);
                *reinterpret_cast<float2*>(&C[(long long)(row + 8) * ldc + col]) = make_float2(v10, v11);
            }
        }
    }
}

// ------------------------------------------------------------------
// fp32 -> fp16 convert
// ------------------------------------------------------------------
__global__ void __launch_bounds__(256) k_f2h(const float4* __restrict__ in,
                                             __half2* __restrict__ out, long long n4) {
    const long long i = (long long)blockIdx.x * blockDim.x + threadIdx.x;
    if (i < n4) {
        float4 v = in[i];
        out[2 * i]     = __floats2half2_rn(v.x, v.y);
        out[2 * i + 1] = __floats2half2_rn(v.z, v.w);
    }
}

// ------------------------------------------------------------------
// Softmax: fp16 scores -> fp16 probs (plain loads; no streaming hints)
// One block per row; 256 thr x 8 halves (one uint4) each.
// ------------------------------------------------------------------
__global__ void __launch_bounds__(256) k_softmax(const __half* __restrict__ S,
                                                 __half* __restrict__ P) {
    __shared__ float red_max[8];
    __shared__ float red_sum[8];
    const long long row = blockIdx.x;
    const int t = threadIdx.x;

    const uint4* src = reinterpret_cast<const uint4*>(S + row * (long long)L_DIM);
    uint4 v = src[t];

    __half2 h0 = *reinterpret_cast<__half2*>(&v.x);
    __half2 h1 = *reinterpret_cast<__half2*>(&v.y);
    __half2 h2 = *reinterpret_cast<__half2*>(&v.z);
    __half2 h3 = *reinterpret_cast<__half2*>(&v.w);

    float f[8];
    { float2 t2;
      t2 = __half22float2(h0); f[0] = t2.x; f[1] = t2.y;
      t2 = __half22float2(h1); f[2] = t2.x; f[3] = t2.y;
      t2 = __half22float2(h2); f[4] = t2.x; f[5] = t2.y;
      t2 = __half22float2(h3); f[6] = t2.x; f[7] = t2.y; }

    float m = f[0];
    #pragma unroll
    for (int i = 1; i < 8; i++) m = fmaxf(m, f[i]);
    #pragma unroll
    for (int o = 16; o; o >>= 1) m = fmaxf(m, __shfl_xor_sync(0xFFFFFFFFu, m, o));
    if ((t & 31) == 0) red_max[t >> 5] = m;
    __syncthreads();
    float mall = red_max[0];
    #pragma unroll
    for (int i = 1; i < 8; i++) mall = fmaxf(mall, red_max[i]);

    float sum = 0.f;
    #pragma unroll
    for (int i = 0; i < 8; i++) { f[i] = __expf(f[i] - mall); sum += f[i]; }
    #pragma unroll
    for (int o = 16; o; o >>= 1) sum += __shfl_xor_sync(0xFFFFFFFFu, sum, o);
    if ((t & 31) == 0) red_sum[t >> 5] = sum;
    __syncthreads();
    float stot = 0.f;
    #pragma unroll
    for (int i = 0; i < 8; i++) stot += red_sum[i];
    const float inv = 1.0f / stot;

    uint4 o;
    __half2 w0 = __floats2half2_rn(f[0] * inv, f[1] * inv);
    __half2 w1 = __floats2half2_rn(f[2] * inv, f[3] * inv);
    __half2 w2 = __floats2half2_rn(f[4] * inv, f[5] * inv);
    __half2 w3 = __floats2half2_rn(f[6] * inv, f[7] * inv);
    o.x = *reinterpret_cast<uint32_t*>(&w0);
    o.y = *reinterpret_cast<uint32_t*>(&w1);
    o.z = *reinterpret_cast<uint32_t*>(&w2);
    o.w = *reinterpret_cast<uint32_t*>(&w3);
    reinterpret_cast<uint4*>(P + row * (long long)L_DIM)[t] = o;
}

// ------------------------------------------------------------------
// Host
// ------------------------------------------------------------------
extern "C" void kernel_launch(void* const* d_in, const int* in_sizes, int n_in,
                              void* d_out, int out_size) {
    const float* x    = (const float*)d_in[0];
    const float* Wqkv = (const float*)d_in[1];
    const float* bqkv = (const float*)d_in[2];
    const float* Wo   = (const float*)d_in[3];
    const float* bo   = (const float*)d_in[4];
    float* out = (float*)d_out;

    __half *xh, *wqkvh, *woh, *qkv, *scores, *attn, *ctx;
    cudaGetSymbolAddress((void**)&xh, g_xh);
    cudaGetSymbolAddress((void**)&wqkvh, g_wqkv);
    cudaGetSymbolAddress((void**)&woh, g_wo);
    cudaGetSymbolAddress((void**)&qkv, g_qkv);
    cudaGetSymbolAddress((void**)&scores, g_scores);
    cudaGetSymbolAddress((void**)&attn, g_attn);
    cudaGetSymbolAddress((void**)&ctx, g_ctx);

    static bool attr_done = false;
    if (!attr_done) {
        cudaFuncSetAttribute(gemm_mma<1>, cudaFuncAttributeMaxDynamicSharedMemorySize, SMEM_DYN);
        cudaFuncSetAttribute(gemm_mma<2>, cudaFuncAttributeMaxDynamicSharedMemorySize, SMEM_DYN);
        cudaFuncSetAttribute(gemm_mma<3>, cudaFuncAttributeMaxDynamicSharedMemorySize, SMEM_DYN);
        cudaFuncSetAttribute(gemm_mma<4>, cudaFuncAttributeMaxDynamicSharedMemorySize, SMEM_DYN);
        attr_done = true;
    }

    {
        const long long nx = (long long)M1 * E_DIM / 4;
        const long long nw = (long long)H_DIM * F3 * E_DIM / 4;
        const long long no = (long long)H_DIM * E_DIM * E_DIM / 4;
        k_f2h<<<(unsigned)((nx + 255) / 256), 256>>>((const float4*)x, (__half2*)xh, nx);
        k_f2h<<<(unsigned)((nw + 255) / 256), 256>>>((const float4*)Wqkv, (__half2*)wqkvh, nw);
        k_f2h<<<(unsigned)((no + 255) / 256), 256>>>((const float4*)Wo, (__half2*)woh, no);
    }

    gemm_mma<1><<<dim3(F3 / BN, M1 / BM, H_DIM), NTHR, SMEM_DYN>>>(xh, wqkvh, bqkv, qkv);
    gemm_mma<2><<<dim3(L_DIM / BN, L_DIM / BM, H_DIM * N_DIM), NTHR, SMEM_DYN>>>(qkv, qkv, nullptr, scores);
    k_softmax<<<H_DIM * N_DIM * L_DIM, 256>>>(scores, attn);
    gemm_mma<3><<<dim3(E_DIM / BN, L_DIM / BM, H_DIM * N_DIM), NTHR, SMEM_DYN>>>(attn, qkv, nullptr, ctx);
    gemm_mma<4><<<dim3(E_DIM / BN, M1 / BM, 1), NTHR, SMEM_DYN>>>(ctx, woh, bo, out);
}

// round 15
// speedup vs baseline: 1.0271x; 1.0208x over previous
#include <cuda_runtime.h>
#include <cuda_fp16.h>
#include <cstdint>

#define L_DIM 2048
#define N_DIM 4
#define E_DIM 1024
#define H_DIM 8
#define M1    (L_DIM * N_DIM)   // 8192
#define F3    (3 * E_DIM)       // 3072

// ------------------------------------------------------------------
// Scratch (__device__ globals; allocation-free)
// ------------------------------------------------------------------
__device__ __half g_xh  [(long long)M1 * E_DIM];
__device__ __half g_wqkv[(long long)H_DIM * F3 * E_DIM];
__device__ __half g_wo  [(long long)H_DIM * E_DIM * E_DIM];
__device__ __half g_qkv [(long long)H_DIM * M1 * F3];
__device__ __half g_scores[(long long)H_DIM * N_DIM * L_DIM * L_DIM];  // fp16 scores
__device__ __half g_attn[(long long)H_DIM * N_DIM * L_DIM * L_DIM];
__device__ __half g_ctx [(long long)H_DIM * M1 * E_DIM];

// ------------------------------------------------------------------
// Tile config: block 128x128, BK=64, 3-stage cp.async,
// 4 warps (128 thr), warp tile 64x64.
// ------------------------------------------------------------------
#define BM 128
#define BN 128
#define BK 64
#define NSTAGE 3
#define NTHR 128

#define A_SLOT_B 16384
#define B_SLOT_B 16384
#define STAGE_B  (A_SLOT_B + B_SLOT_B)
#define SMEM_DYN (NSTAGE * STAGE_B)   // 98304 B

// ------------------------------------------------------------------
// PTX helpers
// ------------------------------------------------------------------
__device__ __forceinline__ uint32_t smem_u32(const void* p) {
    uint32_t a;
    asm("{ .reg .u64 t; cvta.to.shared.u64 t, %1; cvt.u32.u64 %0, t; }" : "=r"(a) : "l"(p));
    return a;
}
__device__ __forceinline__ void cp_async16(uint32_t dst, const void* src) {
    asm volatile("cp.async.cg.shared.global [%0], [%1], 16;" :: "r"(dst), "l"(src));
}
__device__ __forceinline__ void ldsm_x4(uint32_t& r0, uint32_t& r1, uint32_t& r2, uint32_t& r3,
                                        uint32_t addr) {
    asm volatile("ldmatrix.sync.aligned.m8n8.x4.shared.b16 {%0,%1,%2,%3}, [%4];"
                 : "=r"(r0), "=r"(r1), "=r"(r2), "=r"(r3) : "r"(addr));
}
__device__ __forceinline__ void ldsm_x4_t(uint32_t& r0, uint32_t& r1, uint32_t& r2, uint32_t& r3,
                                          uint32_t addr) {
    asm volatile("ldmatrix.sync.aligned.m8n8.x4.trans.shared.b16 {%0,%1,%2,%3}, [%4];"
                 : "=r"(r0), "=r"(r1), "=r"(r2), "=r"(r3) : "r"(addr));
}
__device__ __forceinline__ void mma_f16(float c[4], const uint32_t a[4], const uint32_t b[2]) {
    asm volatile(
        "mma.sync.aligned.m16n8k16.row.col.f32.f16.f16.f32 "
        "{%0,%1,%2,%3}, {%4,%5,%6,%7}, {%8,%9}, {%0,%1,%2,%3};"
        : "+f"(c[0]), "+f"(c[1]), "+f"(c[2]), "+f"(c[3])
        : "r"(a[0]), "r"(a[1]), "r"(a[2]), "r"(a[3]), "r"(b[0]), "r"(b[1]));
}

// Swizzled byte offsets (rows of 128B: 8 x 16B chunks, chunk ^= row&7)
__device__ __forceinline__ uint32_t sw_ab(int row, int kc) {
    return (uint32_t)(row * 128 + ((((kc >> 3) & 7) ^ (row & 7)) << 4));
}
// kn layout: 64 rows x 256B
__device__ __forceinline__ uint32_t sw_kn(int krow, int nc) {
    return (uint32_t)(krow * 256 + ((nc >> 6) << 7) + ((((nc >> 3) & 7) ^ (krow & 7)) << 4));
}

// ------------------------------------------------------------------
// Templated GEMM. STAGE:
//  1: qkv(h) = x @ Wqkv^T + bqkv       A[m][k] B[n][k]  -> C fp16
//  2: scores = scale * q @ k^T         strided fp16     -> C fp16
//  3: ctx(h) = attn @ V                B is [k][n]      -> C fp16
//  4: out = sum_h ctx[h]@Wo[h]^T + b   K loop over h    -> C fp32
// ------------------------------------------------------------------
template <int STAGE>
__global__ void __launch_bounds__(NTHR, 2) gemm_mma(
    const __half* __restrict__ Ain, const __half* __restrict__ Bin,
    const float* __restrict__ bias, void* __restrict__ Cout)
{
    constexpr bool BKN = (STAGE == 3);
    constexpr bool CH  = (STAGE != 4);   // fp16 output for stages 1,2,3
    constexpr int  NKT = (STAGE == 3) ? (L_DIM / BK)
                        : (STAGE == 4 ? H_DIM * (E_DIM / BK) : (E_DIM / BK));
    constexpr float alpha = (STAGE == 2) ? 0.03125f : 1.0f;

    extern __shared__ __align__(1024) char smem[];
    __shared__ float s_bias[BN];

    const int tid  = threadIdx.x;
    const int warp = tid >> 5;
    const int lane = tid & 31;
    const int wm   = warp >> 1;
    const int wn   = warp & 1;
    const int n0   = blockIdx.x * BN;
    const int m0   = blockIdx.y * BM;
    const int bz   = blockIdx.z;
    const int h    = bz >> 2;
    const int nn   = bz & 3;

    const uint32_t s_base = smem_u32(smem);

    for (int i = tid; i < BN; i += NTHR) {
        if (STAGE == 1) {
            s_bias[i] = bias[(long long)bz * F3 + n0 + i];
        } else if (STAGE == 4) {
            float s = 0.f;
            #pragma unroll
            for (int hh = 0; hh < H_DIM; hh++) s += bias[(long long)hh * E_DIM + n0 + i];
            s_bias[i] = s;
        } else {
            s_bias[i] = 0.f;
        }
    }

    const __half* Ab;
    const __half* Bb;
    long long ldA, ldB;
    if (STAGE == 1) {
        Ab = Ain;                                ldA = E_DIM;
        Bb = Bin + (long long)bz * F3 * E_DIM;   ldB = E_DIM;
    } else if (STAGE == 2) {
        const __half* q = Ain + (long long)h * M1 * F3 + (long long)nn * F3;
        Ab = q;          ldA = (long long)N_DIM * F3;
        Bb = q + E_DIM;  ldB = (long long)N_DIM * F3;
    } else if (STAGE == 3) {
        Ab = Ain + (long long)bz * L_DIM * L_DIM;                           ldA = L_DIM;
        Bb = Bin + (long long)h * M1 * F3 + (long long)nn * F3 + 2 * E_DIM; ldB = (long long)N_DIM * F3;
    } else {
        Ab = Ain; ldA = E_DIM;
        Bb = Bin; ldB = E_DIM;
    }

    // One quarter of the tile copy: chunk 0/1 = A halves, 2/3 = B halves.
    auto load_chunk = [&](int kt, int slot, int chunk) {
        const __half* Abase = Ab;
        const __half* Bbase = Bb;
        int kk;
        if (STAGE == 4) {
            const int hh = kt >> 4;
            kk = (kt & 15) * BK;
            Abase = Ab + (long long)hh * M1 * E_DIM;
            Bbase = Bb + (long long)hh * E_DIM * E_DIM;
        } else {
            kk = kt * BK;
        }
        const uint32_t a_sl = s_base + slot * STAGE_B;
        const uint32_t b_sl = a_sl + A_SLOT_B;
        if (chunk < 2) {
            #pragma unroll
            for (int i = chunk * 4; i < chunk * 4 + 4; i++) {
                const int c = tid + i * NTHR;
                const int row = c >> 3;
                const int kc = (c & 7) << 3;
                const __half* src = Abase + (long long)(m0 + row) * ldA + kk + kc;
                cp_async16(a_sl + sw_ab(row, kc), src);
            }
        } else if (!BKN) {
            #pragma unroll
            for (int i = (chunk - 2) * 4; i < (chunk - 2) * 4 + 4; i++) {
                const int c = tid + i * NTHR;
                const int row = c >> 3;
                const int kc = (c & 7) << 3;
                const __half* src = Bbase + (long long)(n0 + row) * ldB + kk + kc;
                cp_async16(b_sl + sw_ab(row, kc), src);
            }
        } else {
            #pragma unroll
            for (int i = (chunk - 2) * 4; i < (chunk - 2) * 4 + 4; i++) {
                const int c = tid + i * NTHR;
                const int krow = c >> 4;
                const int nc = (c & 15) << 3;
                const __half* src = Bbase + (long long)(kk + krow) * ldB + n0 + nc;
                cp_async16(b_sl + sw_kn(krow, nc), src);
            }
        }
    };
    auto load_tile = [&](int kt, int slot) {
        load_chunk(kt, slot, 0);
        load_chunk(kt, slot, 1);
        load_chunk(kt, slot, 2);
        load_chunk(kt, slot, 3);
        asm volatile("cp.async.commit_group;" ::: "memory");
    };

    float acc[4][8][4] = {};

    load_tile(0, 0);
    load_tile(1, 1);
    asm volatile("cp.async.wait_group 1;" ::: "memory");
    __syncthreads();

    const int grp = lane >> 3;
    const int lr  = lane & 7;
    const int arow = lane & 15;
    const int asel = lane >> 4;

    // Ping-pong fragment buffers
    uint32_t afb[2][4][4];
    uint32_t bfb[2][8][2];

    auto load_frags = [&](uint32_t As, uint32_t Bs, int ks, int buf) {
        #pragma unroll
        for (int mi = 0; mi < 4; mi++) {
            const int row = wm * 64 + mi * 16 + arow;
            const int kc = ks * 16 + asel * 8;
            ldsm_x4(afb[buf][mi][0], afb[buf][mi][1], afb[buf][mi][2], afb[buf][mi][3],
                    As + sw_ab(row, kc));
        }
        #pragma unroll
        for (int pair = 0; pair < 4; pair++) {
            uint32_t r0, r1, r2, r3;
            if (!BKN) {
                const int nrow = wn * 64 + pair * 16 + ((grp >> 1) << 3) + lr;
                const int kc = ks * 16 + ((grp & 1) << 3);
                ldsm_x4(r0, r1, r2, r3, Bs + sw_ab(nrow, kc));
            } else {
                const int krow = ks * 16 + ((grp & 1) << 3) + lr;
                const int ncol = wn * 64 + pair * 16 + ((grp >> 1) << 3);
                ldsm_x4_t(r0, r1, r2, r3, Bs + sw_kn(krow, ncol));
            }
            bfb[buf][pair * 2][0]     = r0;
            bfb[buf][pair * 2][1]     = r1;
            bfb[buf][pair * 2 + 1][0] = r2;
            bfb[buf][pair * 2 + 1][1] = r3;
        }
    };

    // Half-burst: 16 MMAs covering mi = {2*half, 2*half+1}, all ni.
    auto mma_half = [&](int buf, int half) {
        #pragma unroll
        for (int mi = 2 * half; mi < 2 * half + 2; mi++)
            #pragma unroll
            for (int ni = 0; ni < 8; ni++)
                mma_f16(acc[mi][ni], afb[buf][mi], bfb[buf][ni]);
    };

    // Prologue: ks0 fragments of kt=0 pre-loaded into buffer 0.
    {
        const uint32_t As0 = s_base;
        load_frags(As0, As0 + A_SLOT_B, 0, 0);
    }

    for (int kt = 0; kt < NKT; kt++) {
        const int slot = kt % NSTAGE;
        const uint32_t As = s_base + slot * STAGE_B;
        const uint32_t Bs = As + A_SLOT_B;
        const bool pref = (kt + 2 < NKT);
        const int pslot = (kt + 2) % NSTAGE;

        // Interleave: cp.async chunks are scattered between half-bursts so
        // no single LSU burst precedes the MMAs it must hide under.
        mma_half(0, 0);                          // ks0 first half
        load_frags(As, Bs, 1, 1);                // ks1 -> b1
        mma_half(0, 1);                          // ks0 second half

        if (pref) load_chunk(kt + 2, pslot, 0);
        load_frags(As, Bs, 2, 0);                // ks2 -> b0
        mma_half(1, 0);                          // ks1 first half
        if (pref) load_chunk(kt + 2, pslot, 1);
        mma_half(1, 1);                          // ks1 second half
        if (pref) load_chunk(kt + 2, pslot, 2);
        load_frags(As, Bs, 3, 1);                // ks3 -> b1
        mma_half(0, 0);                          // ks2 first half
        if (pref) {
            load_chunk(kt + 2, pslot, 3);
            asm volatile("cp.async.commit_group;" ::: "memory");
        }

        if (pref) {
            asm volatile("cp.async.wait_group 1;" ::: "memory");
        } else {
            asm volatile("cp.async.wait_group 0;" ::: "memory");
        }
        __syncthreads();

        mma_half(0, 1);                          // ks2 second half

        // Cross-kt prefetch (slot kt+1 complete, barrier passed).
        {
            const uint32_t nAs = s_base + ((kt + 1) % NSTAGE) * STAGE_B;
            load_frags(nAs, nAs + A_SLOT_B, 0, 0);
        }

        mma_half(1, 0);                          // ks3 first half
        mma_half(1, 1);                          // ks3 second half
    }

    // ---------------- epilogue ----------------
    const int r  = lane >> 2;
    const int cl = lane & 3;

    long long ldc, coff;
    if (STAGE == 1) {
        ldc = F3;    coff = ((long long)bz * M1 + m0) * F3 + n0;
    } else if (STAGE == 2) {
        ldc = L_DIM; coff = ((long long)bz * L_DIM + m0) * L_DIM + n0;
    } else if (STAGE == 3) {
        ldc = (long long)N_DIM * E_DIM;
        coff = (long long)h * M1 * E_DIM + ((long long)m0 * N_DIM + nn) * E_DIM + n0;
    } else {
        ldc = E_DIM; coff = (long long)m0 * E_DIM + n0;
    }

    #pragma unroll
    for (int mi = 0; mi < 4; mi++) {
        #pragma unroll
        for (int ni = 0; ni < 8; ni++) {
            const int row = wm * 64 + mi * 16 + r;
            const int col = wn * 64 + ni * 8 + cl * 2;
            const float v00 = acc[mi][ni][0] * alpha + s_bias[col];
            const float v01 = acc[mi][ni][1] * alpha + s_bias[col + 1];
            const float v10 = acc[mi][ni][2] * alpha + s_bias[col];
            const float v11 = acc[mi][ni][3] * alpha + s_bias[col + 1];
            if (CH) {
                __half* C = (__half*)Cout + coff;
                *reinterpret_cast<__half2*>(&C[(long long)row * ldc + col]) =
                    __floats2half2_rn(v00, v01);
                *reinterpret_cast<__half2*>(&C[(long long)(row + 8) * ldc + col]) =
                    __floats2half2_rn(v10, v11);
            } else {
                float* C = (float*)Cout + coff;
                *reinterpret_cast<float2*>(&C[(long long)row * ldc + col])       = make_float2(v00, v01);
                *reinterpret_cast<float2*>(&C[(long long)(row + 8) * ldc + col]) = make_float2(v10, v11);
            }
        }
    }
}

// ------------------------------------------------------------------
// Fused fp32 -> fp16 convert for all three inputs (single launch)
// ------------------------------------------------------------------
__global__ void __launch_bounds__(256) k_f2h_all(
    const float4* __restrict__ inx,  __half2* __restrict__ outx,  long long nx,
    const float4* __restrict__ inw,  __half2* __restrict__ outw,  long long nw,
    const float4* __restrict__ ino,  __half2* __restrict__ outo,  long long no)
{
    const long long total = nx + nw + no;
    for (long long i = (long long)blockIdx.x * blockDim.x + threadIdx.x;
         i < total; i += (long long)gridDim.x * blockDim.x) {
        const float4* in;
        __half2* out;
        long long j = i;
        if (j < nx)            { in = inx; out = outx; }
        else if ((j -= nx) < nw) { in = inw; out = outw; }
        else                   { j -= nw; in = ino; out = outo; }
        float4 v = in[j];
        out[2 * j]     = __floats2half2_rn(v.x, v.y);
        out[2 * j + 1] = __floats2half2_rn(v.z, v.w);
    }
}

// ------------------------------------------------------------------
// Softmax: fp16 scores -> fp16 probs (plain loads)
// ------------------------------------------------------------------
__global__ void __launch_bounds__(256) k_softmax(const __half* __restrict__ S,
                                                 __half* __restrict__ P) {
    __shared__ float red_max[8];
    __shared__ float red_sum[8];
    const long long row = blockIdx.x;
    const int t = threadIdx.x;

    const uint4* src = reinterpret_cast<const uint4*>(S + row * (long long)L_DIM);
    uint4 v = src[t];

    __half2 h0 = *reinterpret_cast<__half2*>(&v.x);
    __half2 h1 = *reinterpret_cast<__half2*>(&v.y);
    __half2 h2 = *reinterpret_cast<__half2*>(&v.z);
    __half2 h3 = *reinterpret_cast<__half2*>(&v.w);

    float f[8];
    { float2 t2;
      t2 = __half22float2(h0); f[0] = t2.x; f[1] = t2.y;
      t2 = __half22float2(h1); f[2] = t2.x; f[3] = t2.y;
      t2 = __half22float2(h2); f[4] = t2.x; f[5] = t2.y;
      t2 = __half22float2(h3); f[6] = t2.x; f[7] = t2.y; }

    float m = f[0];
    #pragma unroll
    for (int i = 1; i < 8; i++) m = fmaxf(m, f[i]);
    #pragma unroll
    for (int o = 16; o; o >>= 1) m = fmaxf(m, __shfl_xor_sync(0xFFFFFFFFu, m, o));
    if ((t & 31) == 0) red_max[t >> 5] = m;
    __syncthreads();
    float mall = red_max[0];
    #pragma unroll
    for (int i = 1; i < 8; i++) mall = fmaxf(mall, red_max[i]);

    float sum = 0.f;
    #pragma unroll
    for (int i = 0; i < 8; i++) { f[i] = __expf(f[i] - mall); sum += f[i]; }
    #pragma unroll
    for (int o = 16; o; o >>= 1) sum += __shfl_xor_sync(0xFFFFFFFFu, sum, o);
    if ((t & 31) == 0) red_sum[t >> 5] = sum;
    __syncthreads();
    float stot = 0.f;
    #pragma unroll
    for (int i = 0; i < 8; i++) stot += red_sum[i];
    const float inv = 1.0f / stot;

    uint4 o;
    __half2 w0 = __floats2half2_rn(f[0] * inv, f[1] * inv);
    __half2 w1 = __floats2half2_rn(f[2] * inv, f[3] * inv);
    __half2 w2 = __floats2half2_rn(f[4] * inv, f[5] * inv);
    __half2 w3 = __floats2half2_rn(f[6] * inv, f[7] * inv);
    o.x = *reinterpret_cast<uint32_t*>(&w0);
    o.y = *reinterpret_cast<uint32_t*>(&w1);
    o.z = *reinterpret_cast<uint32_t*>(&w2);
    o.w = *reinterpret_cast<uint32_t*>(&w3);
    reinterpret_cast<uint4*>(P + row * (long long)L_DIM)[t] = o;
}

// ------------------------------------------------------------------
// Host
// ------------------------------------------------------------------
extern "C" void kernel_launch(void* const* d_in, const int* in_sizes, int n_in,
                              void* d_out, int out_size) {
    const float* x    = (const float*)d_in[0];
    const float* Wqkv = (const float*)d_in[1];
    const float* bqkv = (const float*)d_in[2];
    const float* Wo   = (const float*)d_in[3];
    const float* bo   = (const float*)d_in[4];
    float* out = (float*)d_out;

    __half *xh, *wqkvh, *woh, *qkv, *scores, *attn, *ctx;
    cudaGetSymbolAddress((void**)&xh, g_xh);
    cudaGetSymbolAddress((void**)&wqkvh, g_wqkv);
    cudaGetSymbolAddress((void**)&woh, g_wo);
    cudaGetSymbolAddress((void**)&qkv, g_qkv);
    cudaGetSymbolAddress((void**)&scores, g_scores);
    cudaGetSymbolAddress((void**)&attn, g_attn);
    cudaGetSymbolAddress((void**)&ctx, g_ctx);

    static bool attr_done = false;
    if (!attr_done) {
        cudaFuncSetAttribute(gemm_mma<1>, cudaFuncAttributeMaxDynamicSharedMemorySize, SMEM_DYN);
        cudaFuncSetAttribute(gemm_mma<2>, cudaFuncAttributeMaxDynamicSharedMemorySize, SMEM_DYN);
        cudaFuncSetAttribute(gemm_mma<3>, cudaFuncAttributeMaxDynamicSharedMemorySize, SMEM_DYN);
        cudaFuncSetAttribute(gemm_mma<4>, cudaFuncAttributeMaxDynamicSharedMemorySize, SMEM_DYN);
        attr_done = true;
    }

    {
        const long long nx = (long long)M1 * E_DIM / 4;
        const long long nw = (long long)H_DIM * F3 * E_DIM / 4;
        const long long no = (long long)H_DIM * E_DIM * E_DIM / 4;
        k_f2h_all<<<2368, 256>>>((const float4*)x, (__half2*)xh, nx,
                                 (const float4*)Wqkv, (__half2*)wqkvh, nw,
                                 (const float4*)Wo, (__half2*)woh, no);
    }

    gemm_mma<1><<<dim3(F3 / BN, M1 / BM, H_DIM), NTHR, SMEM_DYN>>>(xh, wqkvh, bqkv, qkv);
    gemm_mma<2><<<dim3(L_DIM / BN, L_DIM / BM, H_DIM * N_DIM), NTHR, SMEM_DYN>>>(qkv, qkv, nullptr, scores);
    k_softmax<<<H_DIM * N_DIM * L_DIM, 256>>>(scores, attn);
    gemm_mma<3><<<dim3(E_DIM / BN, L_DIM / BM, H_DIM * N_DIM), NTHR, SMEM_DYN>>>(attn, qkv, nullptr, ctx);
    gemm_mma<4><<<dim3(E_DIM / BN, M1 / BM, 1), NTHR, SMEM_DYN>>>(ctx, woh, bo, out);
}

// round 16
// speedup vs baseline: 1.0334x; 1.0061x over previous
#include <cuda_runtime.h>
#include <cuda_fp16.h>
#include <cstdint>

#define L_DIM 2048
#define N_DIM 4
#define E_DIM 1024
#define H_DIM 8
#define M1    (L_DIM * N_DIM)   // 8192
#define F3    (3 * E_DIM)       // 3072

// ------------------------------------------------------------------
// Scratch (__device__ globals; allocation-free)
// ------------------------------------------------------------------
__device__ __half g_xh  [(long long)M1 * E_DIM];
__device__ __half g_wqkv[(long long)H_DIM * F3 * E_DIM];
__device__ __half g_wo  [(long long)H_DIM * E_DIM * E_DIM];
__device__ __half g_qkv [(long long)H_DIM * M1 * F3];
__device__ __half g_scores[(long long)H_DIM * N_DIM * L_DIM * L_DIM];  // fp16 scores
__device__ __half g_attn[(long long)H_DIM * N_DIM * L_DIM * L_DIM];
__device__ __half g_ctx [(long long)H_DIM * M1 * E_DIM];

// ------------------------------------------------------------------
// Tile config: block 128x128, BK=64, 3-stage cp.async,
// 4 warps (128 thr), warp tile 64x64.
// ------------------------------------------------------------------
#define BM 128
#define BN 128
#define BK 64
#define NSTAGE 3
#define NTHR 128

#define A_SLOT_B 16384
#define B_SLOT_B 16384
#define STAGE_B  (A_SLOT_B + B_SLOT_B)
#define SMEM_DYN (NSTAGE * STAGE_B)   // 98304 B

// ------------------------------------------------------------------
// PTX helpers
// ------------------------------------------------------------------
__device__ __forceinline__ uint32_t smem_u32(const void* p) {
    uint32_t a;
    asm("{ .reg .u64 t; cvta.to.shared.u64 t, %1; cvt.u32.u64 %0, t; }" : "=r"(a) : "l"(p));
    return a;
}
__device__ __forceinline__ void cp_async16(uint32_t dst, const void* src) {
    asm volatile("cp.async.cg.shared.global [%0], [%1], 16;" :: "r"(dst), "l"(src));
}
__device__ __forceinline__ void ldsm_x4(uint32_t& r0, uint32_t& r1, uint32_t& r2, uint32_t& r3,
                                        uint32_t addr) {
    asm volatile("ldmatrix.sync.aligned.m8n8.x4.shared.b16 {%0,%1,%2,%3}, [%4];"
                 : "=r"(r0), "=r"(r1), "=r"(r2), "=r"(r3) : "r"(addr));
}
__device__ __forceinline__ void ldsm_x4_t(uint32_t& r0, uint32_t& r1, uint32_t& r2, uint32_t& r3,
                                          uint32_t addr) {
    asm volatile("ldmatrix.sync.aligned.m8n8.x4.trans.shared.b16 {%0,%1,%2,%3}, [%4];"
                 : "=r"(r0), "=r"(r1), "=r"(r2), "=r"(r3) : "r"(addr));
}
__device__ __forceinline__ void mma_f16(float c[4], const uint32_t a[4], const uint32_t b[2]) {
    asm volatile(
        "mma.sync.aligned.m16n8k16.row.col.f32.f16.f16.f32 "
        "{%0,%1,%2,%3}, {%4,%5,%6,%7}, {%8,%9}, {%0,%1,%2,%3};"
        : "+f"(c[0]), "+f"(c[1]), "+f"(c[2]), "+f"(c[3])
        : "r"(a[0]), "r"(a[1]), "r"(a[2]), "r"(a[3]), "r"(b[0]), "r"(b[1]));
}

// Swizzled byte offsets (rows of 128B: 8 x 16B chunks, chunk ^= row&7)
__device__ __forceinline__ uint32_t sw_ab(int row, int kc) {
    return (uint32_t)(row * 128 + ((((kc >> 3) & 7) ^ (row & 7)) << 4));
}
// kn layout: 64 rows x 256B
__device__ __forceinline__ uint32_t sw_kn(int krow, int nc) {
    return (uint32_t)(krow * 256 + ((nc >> 6) << 7) + ((((nc >> 3) & 7) ^ (krow & 7)) << 4));
}

// ------------------------------------------------------------------
// Templated GEMM. STAGE:
//  1: qkv(h) = x @ Wqkv^T + bqkv       A[m][k] B[n][k]  -> C fp16
//  2: scores = scale * q @ k^T         strided fp16     -> C fp16
//  3: ctx(h) = attn @ V                B is [k][n]      -> C fp16
//  4: out = sum_h ctx[h]@Wo[h]^T + b   K loop over h    -> C fp32
// ------------------------------------------------------------------
template <int STAGE>
__global__ void __launch_bounds__(NTHR, 2) gemm_mma(
    const __half* __restrict__ Ain, const __half* __restrict__ Bin,
    const float* __restrict__ bias, void* __restrict__ Cout)
{
    constexpr bool BKN = (STAGE == 3);
    constexpr bool CH  = (STAGE != 4);   // fp16 output for stages 1,2,3
    constexpr int  NKT = (STAGE == 3) ? (L_DIM / BK)
                        : (STAGE == 4 ? H_DIM * (E_DIM / BK) : (E_DIM / BK));
    constexpr float alpha = (STAGE == 2) ? 0.03125f : 1.0f;

    extern __shared__ __align__(1024) char smem[];
    __shared__ float s_bias[BN];

    const int tid  = threadIdx.x;
    const int warp = tid >> 5;
    const int lane = tid & 31;
    const int wm   = warp >> 1;
    const int wn   = warp & 1;
    const int n0   = blockIdx.x * BN;
    const int m0   = blockIdx.y * BM;
    const int bz   = blockIdx.z;
    const int h    = bz >> 2;
    const int nn   = bz & 3;

    const uint32_t s_base = smem_u32(smem);

    for (int i = tid; i < BN; i += NTHR) {
        if (STAGE == 1) {
            s_bias[i] = bias[(long long)bz * F3 + n0 + i];
        } else if (STAGE == 4) {
            float s = 0.f;
            #pragma unroll
            for (int hh = 0; hh < H_DIM; hh++) s += bias[(long long)hh * E_DIM + n0 + i];
            s_bias[i] = s;
        } else {
            s_bias[i] = 0.f;
        }
    }

    const __half* Ab;
    const __half* Bb;
    long long ldA, ldB;
    if (STAGE == 1) {
        Ab = Ain;                                ldA = E_DIM;
        Bb = Bin + (long long)bz * F3 * E_DIM;   ldB = E_DIM;
    } else if (STAGE == 2) {
        const __half* q = Ain + (long long)h * M1 * F3 + (long long)nn * F3;
        Ab = q;          ldA = (long long)N_DIM * F3;
        Bb = q + E_DIM;  ldB = (long long)N_DIM * F3;
    } else if (STAGE == 3) {
        Ab = Ain + (long long)bz * L_DIM * L_DIM;                           ldA = L_DIM;
        Bb = Bin + (long long)h * M1 * F3 + (long long)nn * F3 + 2 * E_DIM; ldB = (long long)N_DIM * F3;
    } else {
        Ab = Ain; ldA = E_DIM;
        Bb = Bin; ldB = E_DIM;
    }

    // One quarter of the tile copy: chunk 0/1 = A halves, 2/3 = B halves.
    auto load_chunk = [&](int kt, int slot, int chunk) {
        const __half* Abase = Ab;
        const __half* Bbase = Bb;
        int kk;
        if (STAGE == 4) {
            const int hh = kt >> 4;
            kk = (kt & 15) * BK;
            Abase = Ab + (long long)hh * M1 * E_DIM;
            Bbase = Bb + (long long)hh * E_DIM * E_DIM;
        } else {
            kk = kt * BK;
        }
        const uint32_t a_sl = s_base + slot * STAGE_B;
        const uint32_t b_sl = a_sl + A_SLOT_B;
        if (chunk < 2) {
            #pragma unroll
            for (int i = chunk * 4; i < chunk * 4 + 4; i++) {
                const int c = tid + i * NTHR;
                const int row = c >> 3;
                const int kc = (c & 7) << 3;
                const __half* src = Abase + (long long)(m0 + row) * ldA + kk + kc;
                cp_async16(a_sl + sw_ab(row, kc), src);
            }
        } else if (!BKN) {
            #pragma unroll
            for (int i = (chunk - 2) * 4; i < (chunk - 2) * 4 + 4; i++) {
                const int c = tid + i * NTHR;
                const int row = c >> 3;
                const int kc = (c & 7) << 3;
                const __half* src = Bbase + (long long)(n0 + row) * ldB + kk + kc;
                cp_async16(b_sl + sw_ab(row, kc), src);
            }
        } else {
            #pragma unroll
            for (int i = (chunk - 2) * 4; i < (chunk - 2) * 4 + 4; i++) {
                const int c = tid + i * NTHR;
                const int krow = c >> 4;
                const int nc = (c & 15) << 3;
                const __half* src = Bbase + (long long)(kk + krow) * ldB + n0 + nc;
                cp_async16(b_sl + sw_kn(krow, nc), src);
            }
        }
    };
    auto load_tile = [&](int kt, int slot) {
        load_chunk(kt, slot, 0);
        load_chunk(kt, slot, 1);
        load_chunk(kt, slot, 2);
        load_chunk(kt, slot, 3);
        asm volatile("cp.async.commit_group;" ::: "memory");
    };

    float acc[4][8][4] = {};

    load_tile(0, 0);
    load_tile(1, 1);
    asm volatile("cp.async.wait_group 1;" ::: "memory");
    __syncthreads();

    const int grp = lane >> 3;
    const int lr  = lane & 7;
    const int arow = lane & 15;
    const int asel = lane >> 4;

    // Ping-pong fragment buffers
    uint32_t afb[2][4][4];
    uint32_t bfb[2][8][2];

    auto load_frags = [&](uint32_t As, uint32_t Bs, int ks, int buf) {
        #pragma unroll
        for (int mi = 0; mi < 4; mi++) {
            const int row = wm * 64 + mi * 16 + arow;
            const int kc = ks * 16 + asel * 8;
            ldsm_x4(afb[buf][mi][0], afb[buf][mi][1], afb[buf][mi][2], afb[buf][mi][3],
                    As + sw_ab(row, kc));
        }
        #pragma unroll
        for (int pair = 0; pair < 4; pair++) {
            uint32_t r0, r1, r2, r3;
            if (!BKN) {
                const int nrow = wn * 64 + pair * 16 + ((grp >> 1) << 3) + lr;
                const int kc = ks * 16 + ((grp & 1) << 3);
                ldsm_x4(r0, r1, r2, r3, Bs + sw_ab(nrow, kc));
            } else {
                const int krow = ks * 16 + ((grp & 1) << 3) + lr;
                const int ncol = wn * 64 + pair * 16 + ((grp >> 1) << 3);
                ldsm_x4_t(r0, r1, r2, r3, Bs + sw_kn(krow, ncol));
            }
            bfb[buf][pair * 2][0]     = r0;
            bfb[buf][pair * 2][1]     = r1;
            bfb[buf][pair * 2 + 1][0] = r2;
            bfb[buf][pair * 2 + 1][1] = r3;
        }
    };

    // Half-burst: 16 MMAs covering mi = {2*half, 2*half+1}, all ni.
    auto mma_half = [&](int buf, int half) {
        #pragma unroll
        for (int mi = 2 * half; mi < 2 * half + 2; mi++)
            #pragma unroll
            for (int ni = 0; ni < 8; ni++)
                mma_f16(acc[mi][ni], afb[buf][mi], bfb[buf][ni]);
    };

    // Prologue: ks0 fragments of kt=0 pre-loaded into buffer 0.
    {
        const uint32_t As0 = s_base;
        load_frags(As0, As0 + A_SLOT_B, 0, 0);
    }

    for (int kt = 0; kt < NKT; kt++) {
        const int slot = kt % NSTAGE;
        const uint32_t As = s_base + slot * STAGE_B;
        const uint32_t Bs = As + A_SLOT_B;
        const bool pref = (kt + 2 < NKT);
        const int pslot = (kt + 2) % NSTAGE;

        // Interleave: cp.async chunks are scattered between half-bursts so
        // no single LSU burst precedes the MMAs it must hide under.
        mma_half(0, 0);                          // ks0 first half
        load_frags(As, Bs, 1, 1);                // ks1 -> b1
        mma_half(0, 1);                          // ks0 second half

        if (pref) load_chunk(kt + 2, pslot, 0);
        load_frags(As, Bs, 2, 0);                // ks2 -> b0
        mma_half(1, 0);                          // ks1 first half
        if (pref) load_chunk(kt + 2, pslot, 1);
        mma_half(1, 1);                          // ks1 second half
        if (pref) load_chunk(kt + 2, pslot, 2);
        load_frags(As, Bs, 3, 1);                // ks3 -> b1
        mma_half(0, 0);                          // ks2 first half
        if (pref) {
            load_chunk(kt + 2, pslot, 3);
            asm volatile("cp.async.commit_group;" ::: "memory");
        }

        if (pref) {
            asm volatile("cp.async.wait_group 1;" ::: "memory");
        } else {
            asm volatile("cp.async.wait_group 0;" ::: "memory");
        }
        __syncthreads();

        mma_half(0, 1);                          // ks2 second half

        // Cross-kt prefetch (slot kt+1 complete, barrier passed).
        {
            const uint32_t nAs = s_base + ((kt + 1) % NSTAGE) * STAGE_B;
            load_frags(nAs, nAs + A_SLOT_B, 0, 0);
        }

        mma_half(1, 0);                          // ks3 first half
        mma_half(1, 1);                          // ks3 second half
    }

    // ---------------- epilogue ----------------
    const int r  = lane >> 2;
    const int cl = lane & 3;

    long long ldc, coff;
    if (STAGE == 1) {
        ldc = F3;    coff = ((long long)bz * M1 + m0) * F3 + n0;
    } else if (STAGE == 2) {
        ldc = L_DIM; coff = ((long long)bz * L_DIM + m0) * L_DIM + n0;
    } else if (STAGE == 3) {
        ldc = (long long)N_DIM * E_DIM;
        coff = (long long)h * M1 * E_DIM + ((long long)m0 * N_DIM + nn) * E_DIM + n0;
    } else {
        ldc = E_DIM; coff = (long long)m0 * E_DIM + n0;
    }

    #pragma unroll
    for (int mi = 0; mi < 4; mi++) {
        #pragma unroll
        for (int ni = 0; ni < 8; ni++) {
            const int row = wm * 64 + mi * 16 + r;
            const int col = wn * 64 + ni * 8 + cl * 2;
            const float v00 = acc[mi][ni][0] * alpha + s_bias[col];
            const float v01 = acc[mi][ni][1] * alpha + s_bias[col + 1];
            const float v10 = acc[mi][ni][2] * alpha + s_bias[col];
            const float v11 = acc[mi][ni][3] * alpha + s_bias[col + 1];
            if (CH) {
                __half* C = (__half*)Cout + coff;
                *reinterpret_cast<__half2*>(&C[(long long)row * ldc + col]) =
                    __floats2half2_rn(v00, v01);
                *reinterpret_cast<__half2*>(&C[(long long)(row + 8) * ldc + col]) =
                    __floats2half2_rn(v10, v11);
            } else {
                float* C = (float*)Cout + coff;
                *reinterpret_cast<float2*>(&C[(long long)row * ldc + col])       = make_float2(v00, v01);
                *reinterpret_cast<float2*>(&C[(long long)(row + 8) * ldc + col]) = make_float2(v10, v11);
            }
        }
    }
}

// ------------------------------------------------------------------
// Fused fp32 -> fp16 convert for all three inputs (single launch)
// ------------------------------------------------------------------
__global__ void __launch_bounds__(256) k_f2h_all(
    const float4* __restrict__ inx,  __half2* __restrict__ outx,  long long nx,
    const float4* __restrict__ inw,  __half2* __restrict__ outw,  long long nw,
    const float4* __restrict__ ino,  __half2* __restrict__ outo,  long long no)
{
    const long long total = nx + nw + no;
    for (long long i = (long long)blockIdx.x * blockDim.x + threadIdx.x;
         i < total; i += (long long)gridDim.x * blockDim.x) {
        const float4* in;
        __half2* out;
        long long j = i;
        if (j < nx)            { in = inx; out = outx; }
        else if ((j -= nx) < nw) { in = inw; out = outw; }
        else                   { j -= nw; in = ino; out = outo; }
        float4 v = in[j];
        out[2 * j]     = __floats2half2_rn(v.x, v.y);
        out[2 * j + 1] = __floats2half2_rn(v.z, v.w);
    }
}

// ------------------------------------------------------------------
// Softmax: warp-per-row, fp16 in/out, no smem/barriers.
// Block 256 = 8 warps = 8 rows; lane c-th chunk at (c*32+lane)*8 halves
// -> fully coalesced 512B transactions per chunk.
// ------------------------------------------------------------------
__global__ void __launch_bounds__(256) k_softmax(const __half* __restrict__ S,
                                                 __half* __restrict__ P) {
    const int warp = threadIdx.x >> 5;
    const int lane = threadIdx.x & 31;
    const long long row = (long long)blockIdx.x * 8 + warp;

    const uint4* src = reinterpret_cast<const uint4*>(S + row * (long long)L_DIM);
    uint4* dst = reinterpret_cast<uint4*>(P + row * (long long)L_DIM);

    uint4 v[8];
    #pragma unroll
    for (int c = 0; c < 8; c++) v[c] = src[c * 32 + lane];

    // Row max (fp32)
    float m = -1e30f;
    #pragma unroll
    for (int c = 0; c < 8; c++) {
        const uint32_t* w = &v[c].x;
        #pragma unroll
        for (int q = 0; q < 4; q++) {
            float2 f2 = __half22float2(*reinterpret_cast<const __half2*>(&w[q]));
            m = fmaxf(m, fmaxf(f2.x, f2.y));
        }
    }
    #pragma unroll
    for (int o = 16; o; o >>= 1) m = fmaxf(m, __shfl_xor_sync(0xFFFFFFFFu, m, o));

    // exp + sum (fp32), results staged back into v as fp16
    float sum = 0.f;
    #pragma unroll
    for (int c = 0; c < 8; c++) {
        uint32_t* w = &v[c].x;
        #pragma unroll
        for (int q = 0; q < 4; q++) {
            float2 f2 = __half22float2(*reinterpret_cast<const __half2*>(&w[q]));
            const float e0 = __expf(f2.x - m);
            const float e1 = __expf(f2.y - m);
            sum += e0 + e1;
            __half2 h = __floats2half2_rn(e0, e1);
            w[q] = *reinterpret_cast<uint32_t*>(&h);
        }
    }
    #pragma unroll
    for (int o = 16; o; o >>= 1) sum += __shfl_xor_sync(0xFFFFFFFFu, sum, o);
    const float inv = 1.0f / sum;

    // Normalize in fp32, write back
    #pragma unroll
    for (int c = 0; c < 8; c++) {
        uint32_t* w = &v[c].x;
        #pragma unroll
        for (int q = 0; q < 4; q++) {
            float2 f2 = __half22float2(*reinterpret_cast<const __half2*>(&w[q]));
            __half2 h = __floats2half2_rn(f2.x * inv, f2.y * inv);
            w[q] = *reinterpret_cast<uint32_t*>(&h);
        }
        dst[c * 32 + lane] = v[c];
    }
}

// ------------------------------------------------------------------
// Host
// ------------------------------------------------------------------
extern "C" void kernel_launch(void* const* d_in, const int* in_sizes, int n_in,
                              void* d_out, int out_size) {
    const float* x    = (const float*)d_in[0];
    const float* Wqkv = (const float*)d_in[1];
    const float* bqkv = (const float*)d_in[2];
    const float* Wo   = (const float*)d_in[3];
    const float* bo   = (const float*)d_in[4];
    float* out = (float*)d_out;

    __half *xh, *wqkvh, *woh, *qkv, *scores, *attn, *ctx;
    cudaGetSymbolAddress((void**)&xh, g_xh);
    cudaGetSymbolAddress((void**)&wqkvh, g_wqkv);
    cudaGetSymbolAddress((void**)&woh, g_wo);
    cudaGetSymbolAddress((void**)&qkv, g_qkv);
    cudaGetSymbolAddress((void**)&scores, g_scores);
    cudaGetSymbolAddress((void**)&attn, g_attn);
    cudaGetSymbolAddress((void**)&ctx, g_ctx);

    static bool attr_done = false;
    if (!attr_done) {
        cudaFuncSetAttribute(gemm_mma<1>, cudaFuncAttributeMaxDynamicSharedMemorySize, SMEM_DYN);
        cudaFuncSetAttribute(gemm_mma<2>, cudaFuncAttributeMaxDynamicSharedMemorySize, SMEM_DYN);
        cudaFuncSetAttribute(gemm_mma<3>, cudaFuncAttributeMaxDynamicSharedMemorySize, SMEM_DYN);
        cudaFuncSetAttribute(gemm_mma<4>, cudaFuncAttributeMaxDynamicSharedMemorySize, SMEM_DYN);
        attr_done = true;
    }

    {
        const long long nx = (long long)M1 * E_DIM / 4;
        const long long nw = (long long)H_DIM * F3 * E_DIM / 4;
        const long long no = (long long)H_DIM * E_DIM * E_DIM / 4;
        k_f2h_all<<<2368, 256>>>((const float4*)x, (__half2*)xh, nx,
                                 (const float4*)Wqkv, (__half2*)wqkvh, nw,
                                 (const float4*)Wo, (__half2*)woh, no);
    }

    gemm_mma<1><<<dim3(F3 / BN, M1 / BM, H_DIM), NTHR, SMEM_DYN>>>(xh, wqkvh, bqkv, qkv);
    gemm_mma<2><<<dim3(L_DIM / BN, L_DIM / BM, H_DIM * N_DIM), NTHR, SMEM_DYN>>>(qkv, qkv, nullptr, scores);
    k_softmax<<<H_DIM * N_DIM * L_DIM / 8, 256>>>(scores, attn);
    gemm_mma<3><<<dim3(E_DIM / BN, L_DIM / BM, H_DIM * N_DIM), NTHR, SMEM_DYN>>>(attn, qkv, nullptr, ctx);
    gemm_mma<4><<<dim3(E_DIM / BN, M1 / BM, 1), NTHR, SMEM_DYN>>>(ctx, woh, bo, out);
}

// round 17
// speedup vs baseline: 1.0348x; 1.0013x over previous
#include <cuda_runtime.h>
#include <cuda_fp16.h>
#include <cstdint>

#define L_DIM 2048
#define N_DIM 4
#define E_DIM 1024
#define H_DIM 8
#define M1    (L_DIM * N_DIM)   // 8192
#define F3    (3 * E_DIM)       // 3072

// ------------------------------------------------------------------
// Scratch (__device__ globals; allocation-free)
// ------------------------------------------------------------------
__device__ __half g_xh  [(long long)M1 * E_DIM];
__device__ __half g_wqkv[(long long)H_DIM * F3 * E_DIM];
__device__ __half g_wo  [(long long)H_DIM * E_DIM * E_DIM];
__device__ __half g_qkv [(long long)H_DIM * M1 * F3];
__device__ __half g_scores[(long long)H_DIM * N_DIM * L_DIM * L_DIM];  // fp16; softmax in place
__device__ __half g_ctx [(long long)H_DIM * M1 * E_DIM];

// ------------------------------------------------------------------
// Tile config: block 128x128, BK=64, 3-stage cp.async,
// 4 warps (128 thr), warp tile 64x64.
// ------------------------------------------------------------------
#define BM 128
#define BN 128
#define BK 64
#define NSTAGE 3
#define NTHR 128

#define A_SLOT_B 16384
#define B_SLOT_B 16384
#define STAGE_B  (A_SLOT_B + B_SLOT_B)
#define SMEM_DYN (NSTAGE * STAGE_B)   // 98304 B

// ------------------------------------------------------------------
// PTX helpers
// ------------------------------------------------------------------
__device__ __forceinline__ uint32_t smem_u32(const void* p) {
    uint32_t a;
    asm("{ .reg .u64 t; cvta.to.shared.u64 t, %1; cvt.u32.u64 %0, t; }" : "=r"(a) : "l"(p));
    return a;
}
__device__ __forceinline__ void cp_async16(uint32_t dst, const void* src) {
    asm volatile("cp.async.cg.shared.global [%0], [%1], 16;" :: "r"(dst), "l"(src));
}
__device__ __forceinline__ void ldsm_x4(uint32_t& r0, uint32_t& r1, uint32_t& r2, uint32_t& r3,
                                        uint32_t addr) {
    asm volatile("ldmatrix.sync.aligned.m8n8.x4.shared.b16 {%0,%1,%2,%3}, [%4];"
                 : "=r"(r0), "=r"(r1), "=r"(r2), "=r"(r3) : "r"(addr));
}
__device__ __forceinline__ void ldsm_x4_t(uint32_t& r0, uint32_t& r1, uint32_t& r2, uint32_t& r3,
                                          uint32_t addr) {
    asm volatile("ldmatrix.sync.aligned.m8n8.x4.trans.shared.b16 {%0,%1,%2,%3}, [%4];"
                 : "=r"(r0), "=r"(r1), "=r"(r2), "=r"(r3) : "r"(addr));
}
__device__ __forceinline__ void mma_f16(float c[4], const uint32_t a[4], const uint32_t b[2]) {
    asm volatile(
        "mma.sync.aligned.m16n8k16.row.col.f32.f16.f16.f32 "
        "{%0,%1,%2,%3}, {%4,%5,%6,%7}, {%8,%9}, {%0,%1,%2,%3};"
        : "+f"(c[0]), "+f"(c[1]), "+f"(c[2]), "+f"(c[3])
        : "r"(a[0]), "r"(a[1]), "r"(a[2]), "r"(a[3]), "r"(b[0]), "r"(b[1]));
}

// Swizzled byte offsets (rows of 128B: 8 x 16B chunks, chunk ^= row&7)
__device__ __forceinline__ uint32_t sw_ab(int row, int kc) {
    return (uint32_t)(row * 128 + ((((kc >> 3) & 7) ^ (row & 7)) << 4));
}
// kn layout: 64 rows x 256B
__device__ __forceinline__ uint32_t sw_kn(int krow, int nc) {
    return (uint32_t)(krow * 256 + ((nc >> 6) << 7) + ((((nc >> 3) & 7) ^ (krow & 7)) << 4));
}

// ------------------------------------------------------------------
// Templated GEMM. STAGE:
//  1: qkv(h) = x @ Wqkv^T + bqkv       A[m][k] B[n][k]  -> C fp16
//  2: scores = scale * q @ k^T         strided fp16     -> C fp16
//  3: ctx(h) = attn @ V                B is [k][n]      -> C fp16
//  4: out = sum_h ctx[h]@Wo[h]^T + b   K loop over h    -> C fp32
// ------------------------------------------------------------------
template <int STAGE>
__global__ void __launch_bounds__(NTHR, 2) gemm_mma(
    const __half* __restrict__ Ain, const __half* __restrict__ Bin,
    const float* __restrict__ bias, void* __restrict__ Cout)
{
    constexpr bool BKN = (STAGE == 3);
    constexpr bool CH  = (STAGE != 4);   // fp16 output for stages 1,2,3
    constexpr int  NKT = (STAGE == 3) ? (L_DIM / BK)
                        : (STAGE == 4 ? H_DIM * (E_DIM / BK) : (E_DIM / BK));
    constexpr float alpha = (STAGE == 2) ? 0.03125f : 1.0f;

    extern __shared__ __align__(1024) char smem[];
    __shared__ float s_bias[BN];

    const int tid  = threadIdx.x;
    const int warp = tid >> 5;
    const int lane = tid & 31;
    const int wm   = warp >> 1;
    const int wn   = warp & 1;
    const int n0   = blockIdx.x * BN;
    const int m0   = blockIdx.y * BM;
    const int bz   = blockIdx.z;
    const int h    = bz >> 2;
    const int nn   = bz & 3;

    const uint32_t s_base = smem_u32(smem);

    for (int i = tid; i < BN; i += NTHR) {
        if (STAGE == 1) {
            s_bias[i] = bias[(long long)bz * F3 + n0 + i];
        } else if (STAGE == 4) {
            float s = 0.f;
            #pragma unroll
            for (int hh = 0; hh < H_DIM; hh++) s += bias[(long long)hh * E_DIM + n0 + i];
            s_bias[i] = s;
        } else {
            s_bias[i] = 0.f;
        }
    }

    const __half* Ab;
    const __half* Bb;
    long long ldA, ldB;
    if (STAGE == 1) {
        Ab = Ain;                                ldA = E_DIM;
        Bb = Bin + (long long)bz * F3 * E_DIM;   ldB = E_DIM;
    } else if (STAGE == 2) {
        const __half* q = Ain + (long long)h * M1 * F3 + (long long)nn * F3;
        Ab = q;          ldA = (long long)N_DIM * F3;
        Bb = q + E_DIM;  ldB = (long long)N_DIM * F3;
    } else if (STAGE == 3) {
        Ab = Ain + (long long)bz * L_DIM * L_DIM;                           ldA = L_DIM;
        Bb = Bin + (long long)h * M1 * F3 + (long long)nn * F3 + 2 * E_DIM; ldB = (long long)N_DIM * F3;
    } else {
        Ab = Ain; ldA = E_DIM;
        Bb = Bin; ldB = E_DIM;
    }

    // One quarter of the tile copy: chunk 0/1 = A halves, 2/3 = B halves.
    auto load_chunk = [&](int kt, int slot, int chunk) {
        const __half* Abase = Ab;
        const __half* Bbase = Bb;
        int kk;
        if (STAGE == 4) {
            const int hh = kt >> 4;
            kk = (kt & 15) * BK;
            Abase = Ab + (long long)hh * M1 * E_DIM;
            Bbase = Bb + (long long)hh * E_DIM * E_DIM;
        } else {
            kk = kt * BK;
        }
        const uint32_t a_sl = s_base + slot * STAGE_B;
        const uint32_t b_sl = a_sl + A_SLOT_B;
        if (chunk < 2) {
            #pragma unroll
            for (int i = chunk * 4; i < chunk * 4 + 4; i++) {
                const int c = tid + i * NTHR;
                const int row = c >> 3;
                const int kc = (c & 7) << 3;
                const __half* src = Abase + (long long)(m0 + row) * ldA + kk + kc;
                cp_async16(a_sl + sw_ab(row, kc), src);
            }
        } else if (!BKN) {
            #pragma unroll
            for (int i = (chunk - 2) * 4; i < (chunk - 2) * 4 + 4; i++) {
                const int c = tid + i * NTHR;
                const int row = c >> 3;
                const int kc = (c & 7) << 3;
                const __half* src = Bbase + (long long)(n0 + row) * ldB + kk + kc;
                cp_async16(b_sl + sw_ab(row, kc), src);
            }
        } else {
            #pragma unroll
            for (int i = (chunk - 2) * 4; i < (chunk - 2) * 4 + 4; i++) {
                const int c = tid + i * NTHR;
                const int krow = c >> 4;
                const int nc = (c & 15) << 3;
                const __half* src = Bbase + (long long)(kk + krow) * ldB + n0 + nc;
                cp_async16(b_sl + sw_kn(krow, nc), src);
            }
        }
    };
    auto load_tile = [&](int kt, int slot) {
        load_chunk(kt, slot, 0);
        load_chunk(kt, slot, 1);
        load_chunk(kt, slot, 2);
        load_chunk(kt, slot, 3);
        asm volatile("cp.async.commit_group;" ::: "memory");
    };

    float acc[4][8][4] = {};

    load_tile(0, 0);
    load_tile(1, 1);
    asm volatile("cp.async.wait_group 1;" ::: "memory");
    __syncthreads();

    const int grp = lane >> 3;
    const int lr  = lane & 7;
    const int arow = lane & 15;
    const int asel = lane >> 4;

    // Ping-pong fragment buffers
    uint32_t afb[2][4][4];
    uint32_t bfb[2][8][2];

    auto load_frags = [&](uint32_t As, uint32_t Bs, int ks, int buf) {
        #pragma unroll
        for (int mi = 0; mi < 4; mi++) {
            const int row = wm * 64 + mi * 16 + arow;
            const int kc = ks * 16 + asel * 8;
            ldsm_x4(afb[buf][mi][0], afb[buf][mi][1], afb[buf][mi][2], afb[buf][mi][3],
                    As + sw_ab(row, kc));
        }
        #pragma unroll
        for (int pair = 0; pair < 4; pair++) {
            uint32_t r0, r1, r2, r3;
            if (!BKN) {
                const int nrow = wn * 64 + pair * 16 + ((grp >> 1) << 3) + lr;
                const int kc = ks * 16 + ((grp & 1) << 3);
                ldsm_x4(r0, r1, r2, r3, Bs + sw_ab(nrow, kc));
            } else {
                const int krow = ks * 16 + ((grp & 1) << 3) + lr;
                const int ncol = wn * 64 + pair * 16 + ((grp >> 1) << 3);
                ldsm_x4_t(r0, r1, r2, r3, Bs + sw_kn(krow, ncol));
            }
            bfb[buf][pair * 2][0]     = r0;
            bfb[buf][pair * 2][1]     = r1;
            bfb[buf][pair * 2 + 1][0] = r2;
            bfb[buf][pair * 2 + 1][1] = r3;
        }
    };

    // Half-burst: 16 MMAs covering mi = {2*half, 2*half+1}, all ni.
    auto mma_half = [&](int buf, int half) {
        #pragma unroll
        for (int mi = 2 * half; mi < 2 * half + 2; mi++)
            #pragma unroll
            for (int ni = 0; ni < 8; ni++)
                mma_f16(acc[mi][ni], afb[buf][mi], bfb[buf][ni]);
    };

    // Prologue: ks0 fragments of kt=0 pre-loaded into buffer 0.
    {
        const uint32_t As0 = s_base;
        load_frags(As0, As0 + A_SLOT_B, 0, 0);
    }

    for (int kt = 0; kt < NKT; kt++) {
        const int slot = kt % NSTAGE;
        const uint32_t As = s_base + slot * STAGE_B;
        const uint32_t Bs = As + A_SLOT_B;
        const bool pref = (kt + 2 < NKT);
        const int pslot = (kt + 2) % NSTAGE;

        // Interleave: cp.async chunks are scattered between half-bursts so
        // no single LSU burst precedes the MMAs it must hide under.
        mma_half(0, 0);                          // ks0 first half
        load_frags(As, Bs, 1, 1);                // ks1 -> b1
        mma_half(0, 1);                          // ks0 second half

        if (pref) load_chunk(kt + 2, pslot, 0);
        load_frags(As, Bs, 2, 0);                // ks2 -> b0
        mma_half(1, 0);                          // ks1 first half
        if (pref) load_chunk(kt + 2, pslot, 1);
        mma_half(1, 1);                          // ks1 second half
        if (pref) load_chunk(kt + 2, pslot, 2);
        load_frags(As, Bs, 3, 1);                // ks3 -> b1
        mma_half(0, 0);                          // ks2 first half
        if (pref) {
            load_chunk(kt + 2, pslot, 3);
            asm volatile("cp.async.commit_group;" ::: "memory");
        }

        if (pref) {
            asm volatile("cp.async.wait_group 1;" ::: "memory");
        } else {
            asm volatile("cp.async.wait_group 0;" ::: "memory");
        }
        __syncthreads();

        mma_half(0, 1);                          // ks2 second half

        // Cross-kt prefetch (slot kt+1 complete, barrier passed).
        {
            const uint32_t nAs = s_base + ((kt + 1) % NSTAGE) * STAGE_B;
            load_frags(nAs, nAs + A_SLOT_B, 0, 0);
        }

        mma_half(1, 0);                          // ks3 first half
        mma_half(1, 1);                          // ks3 second half
    }

    // ---------------- epilogue ----------------
    const int r  = lane >> 2;
    const int cl = lane & 3;

    long long ldc, coff;
    if (STAGE == 1) {
        ldc = F3;    coff = ((long long)bz * M1 + m0) * F3 + n0;
    } else if (STAGE == 2) {
        ldc = L_DIM; coff = ((long long)bz * L_DIM + m0) * L_DIM + n0;
    } else if (STAGE == 3) {
        ldc = (long long)N_DIM * E_DIM;
        coff = (long long)h * M1 * E_DIM + ((long long)m0 * N_DIM + nn) * E_DIM + n0;
    } else {
        ldc = E_DIM; coff = (long long)m0 * E_DIM + n0;
    }

    #pragma unroll
    for (int mi = 0; mi < 4; mi++) {
        #pragma unroll
        for (int ni = 0; ni < 8; ni++) {
            const int row = wm * 64 + mi * 16 + r;
            const int col = wn * 64 + ni * 8 + cl * 2;
            const float v00 = acc[mi][ni][0] * alpha + s_bias[col];
            const float v01 = acc[mi][ni][1] * alpha + s_bias[col + 1];
            const float v10 = acc[mi][ni][2] * alpha + s_bias[col];
            const float v11 = acc[mi][ni][3] * alpha + s_bias[col + 1];
            if (CH) {
                __half* C = (__half*)Cout + coff;
                *reinterpret_cast<__half2*>(&C[(long long)row * ldc + col]) =
                    __floats2half2_rn(v00, v01);
                *reinterpret_cast<__half2*>(&C[(long long)(row + 8) * ldc + col]) =
                    __floats2half2_rn(v10, v11);
            } else {
                float* C = (float*)Cout + coff;
                *reinterpret_cast<float2*>(&C[(long long)row * ldc + col])       = make_float2(v00, v01);
                *reinterpret_cast<float2*>(&C[(long long)(row + 8) * ldc + col]) = make_float2(v10, v11);
            }
        }
    }
}

// ------------------------------------------------------------------
// Fused fp32 -> fp16 convert for all three inputs (single launch)
// ------------------------------------------------------------------
__global__ void __launch_bounds__(256) k_f2h_all(
    const float4* __restrict__ inx,  __half2* __restrict__ outx,  long long nx,
    const float4* __restrict__ inw,  __half2* __restrict__ outw,  long long nw,
    const float4* __restrict__ ino,  __half2* __restrict__ outo,  long long no)
{
    const long long total = nx + nw + no;
    for (long long i = (long long)blockIdx.x * blockDim.x + threadIdx.x;
         i < total; i += (long long)gridDim.x * blockDim.x) {
        const float4* in;
        __half2* out;
        long long j = i;
        if (j < nx)            { in = inx; out = outx; }
        else if ((j -= nx) < nw) { in = inw; out = outw; }
        else                   { j -= nw; in = ino; out = outo; }
        float4 v = in[j];
        out[2 * j]     = __floats2half2_rn(v.x, v.y);
        out[2 * j + 1] = __floats2half2_rn(v.z, v.w);
    }
}

// ------------------------------------------------------------------
// Softmax: warp-per-row, fp16, IN PLACE (write hits the L2 lines just
// read; no second 268MB buffer churning L2 between stages 2 and 3).
// Block 256 = 8 warps = 8 rows; fully coalesced uint4 chunks.
// ------------------------------------------------------------------
__global__ void __launch_bounds__(256) k_softmax(__half* __restrict__ S) {
    const int warp = threadIdx.x >> 5;
    const int lane = threadIdx.x & 31;
    const long long row = (long long)blockIdx.x * 8 + warp;

    uint4* ptr = reinterpret_cast<uint4*>(S + row * (long long)L_DIM);

    uint4 v[8];
    #pragma unroll
    for (int c = 0; c < 8; c++) v[c] = ptr[c * 32 + lane];

    // Row max (fp32)
    float m = -1e30f;
    #pragma unroll
    for (int c = 0; c < 8; c++) {
        const uint32_t* w = &v[c].x;
        #pragma unroll
        for (int q = 0; q < 4; q++) {
            float2 f2 = __half22float2(*reinterpret_cast<const __half2*>(&w[q]));
            m = fmaxf(m, fmaxf(f2.x, f2.y));
        }
    }
    #pragma unroll
    for (int o = 16; o; o >>= 1) m = fmaxf(m, __shfl_xor_sync(0xFFFFFFFFu, m, o));

    // exp + sum (fp32), staged back into v as fp16
    float sum = 0.f;
    #pragma unroll
    for (int c = 0; c < 8; c++) {
        uint32_t* w = &v[c].x;
        #pragma unroll
        for (int q = 0; q < 4; q++) {
            float2 f2 = __half22float2(*reinterpret_cast<const __half2*>(&w[q]));
            const float e0 = __expf(f2.x - m);
            const float e1 = __expf(f2.y - m);
            sum += e0 + e1;
            __half2 h = __floats2half2_rn(e0, e1);
            w[q] = *reinterpret_cast<uint32_t*>(&h);
        }
    }
    #pragma unroll
    for (int o = 16; o; o >>= 1) sum += __shfl_xor_sync(0xFFFFFFFFu, sum, o);
    const float inv = 1.0f / sum;

    // Normalize in fp32, write back in place
    #pragma unroll
    for (int c = 0; c < 8; c++) {
        uint32_t* w = &v[c].x;
        #pragma unroll
        for (int q = 0; q < 4; q++) {
            float2 f2 = __half22float2(*reinterpret_cast<const __half2*>(&w[q]));
            __half2 h = __floats2half2_rn(f2.x * inv, f2.y * inv);
            w[q] = *reinterpret_cast<uint32_t*>(&h);
        }
        ptr[c * 32 + lane] = v[c];
    }
}

// ------------------------------------------------------------------
// Host
// ------------------------------------------------------------------
extern "C" void kernel_launch(void* const* d_in, const int* in_sizes, int n_in,
                              void* d_out, int out_size) {
    const float* x    = (const float*)d_in[0];
    const float* Wqkv = (const float*)d_in[1];
    const float* bqkv = (const float*)d_in[2];
    const float* Wo   = (const float*)d_in[3];
    const float* bo   = (const float*)d_in[4];
    float* out = (float*)d_out;

    __half *xh, *wqkvh, *woh, *qkv, *scores, *ctx;
    cudaGetSymbolAddress((void**)&xh, g_xh);
    cudaGetSymbolAddress((void**)&wqkvh, g_wqkv);
    cudaGetSymbolAddress((void**)&woh, g_wo);
    cudaGetSymbolAddress((void**)&qkv, g_qkv);
    cudaGetSymbolAddress((void**)&scores, g_scores);
    cudaGetSymbolAddress((void**)&ctx, g_ctx);

    static bool attr_done = false;
    if (!attr_done) {
        cudaFuncSetAttribute(gemm_mma<1>, cudaFuncAttributeMaxDynamicSharedMemorySize, SMEM_DYN);
        cudaFuncSetAttribute(gemm_mma<2>, cudaFuncAttributeMaxDynamicSharedMemorySize, SMEM_DYN);
        cudaFuncSetAttribute(gemm_mma<3>, cudaFuncAttributeMaxDynamicSharedMemorySize, SMEM_DYN);
        cudaFuncSetAttribute(gemm_mma<4>, cudaFuncAttributeMaxDynamicSharedMemorySize, SMEM_DYN);
        attr_done = true;
    }

    {
        const long long nx = (long long)M1 * E_DIM / 4;
        const long long nw = (long long)H_DIM * F3 * E_DIM / 4;
        const long long no = (long long)H_DIM * E_DIM * E_DIM / 4;
        k_f2h_all<<<2368, 256>>>((const float4*)x, (__half2*)xh, nx,
                                 (const float4*)Wqkv, (__half2*)wqkvh, nw,
                                 (const float4*)Wo, (__half2*)woh, no);
    }

    gemm_mma<1><<<dim3(F3 / BN, M1 / BM, H_DIM), NTHR, SMEM_DYN>>>(xh, wqkvh, bqkv, qkv);
    gemm_mma<2><<<dim3(L_DIM / BN, L_DIM / BM, H_DIM * N_DIM), NTHR, SMEM_DYN>>>(qkv, qkv, nullptr, scores);
    k_softmax<<<H_DIM * N_DIM * L_DIM / 8, 256>>>(scores);
    gemm_mma<3><<<dim3(E_DIM / BN, L_DIM / BM, H_DIM * N_DIM), NTHR, SMEM_DYN>>>(scores, qkv, nullptr, ctx);
    gemm_mma<4><<<dim3(E_DIM / BN, M1 / BM, 1), NTHR, SMEM_DYN>>>(ctx, woh, bo, out);
}